// round 1
// baseline (speedup 1.0000x reference)
#include <cuda_runtime.h>
#include <cstdint>

// Problem constants
#define BATCH   8
#define SEQ     1024
#define DMODEL  512
#define DINNER  1024
#define DSTATE  16
#define DTRANK  32
#define DCONV   4
#define MTOK    (BATCH*SEQ)          // 8192 tokens
#define NDBC    (DTRANK + 2*DSTATE)  // 64

// ---------------- scratch (static device globals; no allocation) -------------
__device__ float g_xi [MTOK * DINNER];   // pre-conv inner activations
__device__ float g_xc [MTOK * DINNER];   // post-conv silu activations (u)
__device__ float g_dbc[MTOK * NDBC];     // [dt_rank | B | C] projections
__device__ float g_dt [MTOK * DINNER];   // softplus(dt)
__device__ float g_zlast[BATCH * DINNER];
__device__ float g_ylast[BATCH * DINNER];

// ---------------- generic NT tiled SGEMM: C[M,N] = A[M,K(lda)] * B[N,K(ldb)]^T
// EPI: 0 = plain store, 1 = softplus(v + bias[n])
template<int BM, int BN, int BK, int TM, int TN, int EPI>
__global__ void gemm_nt(const float* __restrict__ A, const float* __restrict__ B,
                        float* __restrict__ C, int M, int N, int K,
                        int lda, int ldb,
                        const float* __restrict__ bias)
{
    constexpr int THREADS = (BM/TM) * (BN/TN);
    __shared__ float As[BK][BM];
    __shared__ float Bs[BK][BN];

    const int tid = threadIdx.x;
    const int tn  = tid % (BN/TN);
    const int tm  = tid / (BN/TN);
    const int m0  = blockIdx.y * BM;
    const int n0  = blockIdx.x * BN;

    float acc[TM][TN];
    #pragma unroll
    for (int i = 0; i < TM; ++i)
        #pragma unroll
        for (int j = 0; j < TN; ++j) acc[i][j] = 0.f;

    for (int k0 = 0; k0 < K; k0 += BK) {
        #pragma unroll
        for (int i = tid; i < BM*BK; i += THREADS) {
            int mm = i / BK, kk = i % BK;
            As[kk][mm] = A[(size_t)(m0+mm)*lda + k0 + kk];
        }
        #pragma unroll
        for (int i = tid; i < BN*BK; i += THREADS) {
            int nn = i / BK, kk = i % BK;
            Bs[kk][nn] = B[(size_t)(n0+nn)*ldb + k0 + kk];
        }
        __syncthreads();
        #pragma unroll
        for (int kk = 0; kk < BK; ++kk) {
            float ar[TM], br[TN];
            #pragma unroll
            for (int i = 0; i < TM; ++i) ar[i] = As[kk][tm*TM + i];
            #pragma unroll
            for (int j = 0; j < TN; ++j) br[j] = Bs[kk][tn*TN + j];
            #pragma unroll
            for (int i = 0; i < TM; ++i)
                #pragma unroll
                for (int j = 0; j < TN; ++j)
                    acc[i][j] = fmaf(ar[i], br[j], acc[i][j]);
        }
        __syncthreads();
    }

    #pragma unroll
    for (int i = 0; i < TM; ++i) {
        int m = m0 + tm*TM + i;
        #pragma unroll
        for (int j = 0; j < TN; ++j) {
            int n = n0 + tn*TN + j;
            float v = acc[i][j];
            if (EPI == 1) {
                float t = v + bias[n];
                v = (t > 20.f) ? t : log1pf(__expf(t));
            }
            C[(size_t)m*N + n] = v;
        }
    }
}

// ---------------- depthwise causal conv (kernel=4) + bias + silu --------------
__global__ void conv_silu_kernel(const float* __restrict__ conv_w,
                                 const float* __restrict__ conv_b)
{
    const int m = blockIdx.x;          // token index b*SEQ + l
    const int d = threadIdx.x;         // channel
    const int l = m & (SEQ - 1);
    float acc = conv_b[d];
    #pragma unroll
    for (int k = 0; k < DCONV; ++k) {
        int ll = l + k - (DCONV - 1);
        if (ll >= 0)
            acc = fmaf(conv_w[d*DCONV + k], g_xi[(m + k - (DCONV-1))*DINNER + d], acc);
    }
    g_xc[m*DINNER + d] = acc / (1.f + __expf(-acc)); // silu
}

// ---------------- z at the last token only: z = x[:, -1, :] @ W_in[1024:].T ---
__global__ void zlast_kernel(const float* __restrict__ x,
                             const float* __restrict__ W_in)
{
    const int warp = (blockIdx.x * blockDim.x + threadIdx.x) >> 5; // 0..8191
    const int lane = threadIdx.x & 31;
    const int b = warp >> 10;
    const int d = warp & (DINNER - 1);
    const float* xr = x + ((size_t)b*SEQ + (SEQ-1)) * DMODEL;
    const float* wr = W_in + (size_t)(DINNER + d) * DMODEL;
    float acc = 0.f;
    #pragma unroll 4
    for (int k = lane; k < DMODEL; k += 32) acc = fmaf(xr[k], wr[k], acc);
    #pragma unroll
    for (int off = 16; off; off >>= 1) acc += __shfl_down_sync(0xffffffffu, acc, off);
    if (lane == 0) g_zlast[warp] = acc;
}

// ---------------- selective scan: only final-step y is needed -----------------
// block: 256 threads = 16 channels x 16 states, one batch b, channels dbase..+15
__global__ void scan_kernel(const float* __restrict__ A_log,
                            const float* __restrict__ Dv)
{
    const int b     = blockIdx.x >> 6;            // 512 blocks = 8 b * 64 d-groups
    const int dbase = (blockIdx.x & 63) << 4;
    const int tid = threadIdx.x;
    const int dl  = tid >> 4;                     // 0..15 local channel
    const int s   = tid & 15;                     // state
    const int d   = dbase + dl;

    const float A_s = -__expf(A_log[d*DSTATE + s]);
    float h = 0.f;

    __shared__ float s_dt[64][16];
    __shared__ float s_u [64][16];
    __shared__ float s_B [64][16];

    for (int t0 = 0; t0 < SEQ; t0 += 64) {
        __syncthreads();
        #pragma unroll
        for (int i = 0; i < 4; ++i) {
            int idx = tid + i*256;
            int tt = idx >> 4, c = idx & 15;
            int m = b*SEQ + t0 + tt;
            s_dt[tt][c] = g_dt [m*DINNER + dbase + c];
            s_u [tt][c] = g_xc [m*DINNER + dbase + c];
            s_B [tt][c] = g_dbc[m*NDBC + DTRANK + c];
        }
        __syncthreads();
        #pragma unroll 8
        for (int tt = 0; tt < 64; ++tt) {
            float dtv = s_dt[tt][dl];
            float uv  = s_u [tt][dl];
            float Bv  = s_B [tt][s];
            h = fmaf(__expf(dtv * A_s), h, (dtv * uv) * Bv);
        }
    }

    const int mlast = b*SEQ + (SEQ-1);
    float y = h * g_dbc[mlast*NDBC + DTRANK + DSTATE + s];
    #pragma unroll
    for (int off = 8; off; off >>= 1) y += __shfl_down_sync(0xffffffffu, y, off, 16);
    if (s == 0) {
        float ul = g_xc[mlast*DINNER + d];
        float zl = g_zlast[b*DINNER + d];
        float silu_z = zl / (1.f + __expf(-zl));
        g_ylast[b*DINNER + d] = (y + Dv[d]*ul) * silu_z;
    }
}

// ---------------- tail: out proj (last token) + layernorm + head --------------
__global__ void final_kernel(const float* __restrict__ W_out,
                             const float* __restrict__ ln_g,
                             const float* __restrict__ ln_b,
                             const float* __restrict__ head_W,
                             const float* __restrict__ head_b,
                             float* __restrict__ out)
{
    const int b = blockIdx.x;
    const int j = threadIdx.x; // 512
    __shared__ float sy[DINNER];
    __shared__ float sn[DMODEL];
    __shared__ float rbuf[DMODEL];

    sy[j]         = g_ylast[b*DINNER + j];
    sy[j + 512]   = g_ylast[b*DINNER + 512 + j];
    __syncthreads();

    // last = y_last @ W_out^T
    const float* wr = W_out + (size_t)j * DINNER;
    float a0 = 0.f, a1 = 0.f, a2 = 0.f, a3 = 0.f;
    #pragma unroll 4
    for (int k = 0; k < DINNER; k += 4) {
        float4 w = *reinterpret_cast<const float4*>(wr + k);
        a0 = fmaf(sy[k+0], w.x, a0);
        a1 = fmaf(sy[k+1], w.y, a1);
        a2 = fmaf(sy[k+2], w.z, a2);
        a3 = fmaf(sy[k+3], w.w, a3);
    }
    float last = (a0 + a1) + (a2 + a3);

    // layernorm over 512
    rbuf[j] = last;
    __syncthreads();
    #pragma unroll
    for (int st = 256; st > 0; st >>= 1) {
        if (j < st) rbuf[j] += rbuf[j + st];
        __syncthreads();
    }
    float mu = rbuf[0] / (float)DMODEL;
    __syncthreads();
    float diff = last - mu;
    rbuf[j] = diff * diff;
    __syncthreads();
    #pragma unroll
    for (int st = 256; st > 0; st >>= 1) {
        if (j < st) rbuf[j] += rbuf[j + st];
        __syncthreads();
    }
    float rstd = rsqrtf(rbuf[0] / (float)DMODEL + 1e-5f);
    __syncthreads();

    sn[j] = diff * rstd * ln_g[j] + ln_b[j];
    __syncthreads();

    // head: out = lastn @ head_W^T + head_b
    const float* hw = head_W + (size_t)j * DMODEL;
    float h0 = 0.f, h1 = 0.f, h2 = 0.f, h3 = 0.f;
    #pragma unroll 4
    for (int k = 0; k < DMODEL; k += 4) {
        float4 w = *reinterpret_cast<const float4*>(hw + k);
        h0 = fmaf(sn[k+0], w.x, h0);
        h1 = fmaf(sn[k+1], w.y, h1);
        h2 = fmaf(sn[k+2], w.z, h2);
        h3 = fmaf(sn[k+3], w.w, h3);
    }
    out[b*DMODEL + j] = head_b[j] + (h0 + h1) + (h2 + h3);
}

// ---------------- launch --------------------------------------------------------
extern "C" void kernel_launch(void* const* d_in, const int* in_sizes, int n_in,
                              void* d_out, int out_size)
{
    const float* x      = (const float*)d_in[0];   // [8,1024,512]
    const float* W_in   = (const float*)d_in[1];   // [2048,512]
    const float* conv_w = (const float*)d_in[2];   // [1024,4]
    const float* conv_b = (const float*)d_in[3];   // [1024]
    const float* W_x    = (const float*)d_in[4];   // [64,1024]
    const float* W_dt   = (const float*)d_in[5];   // [1024,32]
    const float* b_dt   = (const float*)d_in[6];   // [1024]
    const float* A_log  = (const float*)d_in[7];   // [1024,16]
    const float* Dv     = (const float*)d_in[8];   // [1024]
    const float* W_out  = (const float*)d_in[9];   // [512,1024]
    const float* ln_g   = (const float*)d_in[10];  // [512]
    const float* ln_b   = (const float*)d_in[11];  // [512]
    const float* head_W = (const float*)d_in[12];  // [512,512]
    const float* head_b = (const float*)d_in[13];  // [512]
    float* out = (float*)d_out;                    // [8,512]

    float* xi  = nullptr; cudaGetSymbolAddress((void**)&xi,  g_xi);
    float* xc  = nullptr; cudaGetSymbolAddress((void**)&xc,  g_xc);
    float* dbc = nullptr; cudaGetSymbolAddress((void**)&dbc, g_dbc);
    float* dtp = nullptr; cudaGetSymbolAddress((void**)&dtp, g_dt);

    // K1: xi = x @ W_in[:1024].T   (M=8192, N=1024, K=512)
    {
        dim3 grid(DINNER/64, MTOK/128);
        gemm_nt<128,64,16,8,4,0><<<grid, 256>>>(x, W_in, xi,
                                                MTOK, DINNER, DMODEL,
                                                DMODEL, DMODEL, nullptr);
    }
    // K2: depthwise conv + silu
    conv_silu_kernel<<<MTOK, DINNER>>>(conv_w, conv_b);

    // K3: dbc = xc @ W_x.T   (M=8192, N=64, K=1024)
    {
        dim3 grid(NDBC/64, MTOK/64);
        gemm_nt<64,64,16,4,4,0><<<grid, 256>>>(xc, W_x, dbc,
                                               MTOK, NDBC, DINNER,
                                               DINNER, DINNER, nullptr);
    }
    // K4: dt = softplus(dbc[:, :32] @ W_dt.T + b_dt)  (M=8192, N=1024, K=32)
    {
        dim3 grid(DINNER/64, MTOK/64);
        gemm_nt<64,64,32,4,4,1><<<grid, 256>>>(dbc, W_dt, dtp,
                                               MTOK, DINNER, DTRANK,
                                               NDBC, DTRANK, b_dt);
    }
    // K5: z at last token
    zlast_kernel<<<(BATCH*DINNER*32)/256, 256>>>(x, W_in);

    // K6: selective scan (final y only)
    scan_kernel<<<BATCH * (DINNER/16), 256>>>(A_log, Dv);

    // K7: out projection (last token) + LN + head
    final_kernel<<<BATCH, DMODEL>>>(W_out, ln_g, ln_b, head_W, head_b, out);
}

// round 4
// speedup vs baseline: 1.7235x; 1.7235x over previous
#include <cuda_runtime.h>
#include <cuda_bf16.h>
#include <cstdint>

// Problem constants
#define BATCH   8
#define SEQ     1024
#define DMODEL  512
#define DINNER  1024
#define DSTATE  16
#define DTRANK  32
#define DCONV   4
#define MTOK    (BATCH*SEQ)          // 8192 tokens
#define NDBC    (DTRANK + 2*DSTATE)  // 64

// ---------------- scratch (static device globals; no allocation) -------------
__device__ float g_xi [MTOK * DINNER];   // pre-conv inner activations
__device__ float g_xc [MTOK * DINNER];   // post-conv silu activations (u)
__device__ float g_dbc[MTOK * NDBC];     // [dt_rank | B | C] projections
__device__ float g_zlast[BATCH * DINNER];
__device__ float g_ylast[BATCH * DINNER];

// ======================= warp-mma helpers (generic sm_80+) ===================
__device__ __forceinline__ uint32_t smem_u32(const void* p) {
    uint32_t a;
    asm("{ .reg .u64 t; cvta.to.shared.u64 t, %1; cvt.u32.u64 %0, t; }" : "=r"(a) : "l"(p));
    return a;
}
__device__ __forceinline__ void ldsm4(uint32_t* r, uint32_t addr) {
    asm volatile("ldmatrix.sync.aligned.m8n8.x4.shared.b16 {%0,%1,%2,%3}, [%4];"
                 : "=r"(r[0]), "=r"(r[1]), "=r"(r[2]), "=r"(r[3]) : "r"(addr));
}
__device__ __forceinline__ void mma_bf16(float* d, const uint32_t* a,
                                         uint32_t b0, uint32_t b1) {
    asm volatile("mma.sync.aligned.m16n8k16.row.col.f32.bf16.bf16.f32 "
                 "{%0,%1,%2,%3}, {%4,%5,%6,%7}, {%8,%9}, {%0,%1,%2,%3};"
                 : "+f"(d[0]), "+f"(d[1]), "+f"(d[2]), "+f"(d[3])
                 : "r"(a[0]), "r"(a[1]), "r"(a[2]), "r"(a[3]), "r"(b0), "r"(b1));
}
__device__ __forceinline__ uint32_t pack_bf16x2(float x, float y) {
    __nv_bfloat16 hx = __float2bfloat16(x), hy = __float2bfloat16(y);
    return ((uint32_t)__bfloat16_as_ushort(hy) << 16) | (uint32_t)__bfloat16_as_ushort(hx);
}

// ============ tensor-core NT GEMM with hi/lo bf16 split (≈fp32 accuracy) ======
// C[M,N] = A[M,K] @ B[N,K]^T. Block tile 128 x BN, K chunk 32.
// 8 warps: 4 along M x 2 along N; warp tile 32 x (BN/2).
template<int BN>
__global__ __launch_bounds__(256)
void gemm_mma(const float* __restrict__ A, const float* __restrict__ Bm,
              float* __restrict__ C, int K, int lda, int ldb, int ldc)
{
    constexpr int BM = 128, BK = 32;
    constexpr int WN = BN / 2;         // warp n-extent
    constexpr int NT = WN / 8;         // 8-wide n-tiles per warp
    constexpr int PITCH = BK + 8;      // bf16 elems per smem row (80B, 16B-aligned)

    __shared__ __align__(16) uint16_t sAh[BM*PITCH], sAl[BM*PITCH];
    __shared__ __align__(16) uint16_t sBh[BN*PITCH], sBl[BN*PITCH];

    const int tid  = threadIdx.x;
    const int wid  = tid >> 5;
    const int lane = tid & 31;
    const int warp_m = wid & 3;
    const int warp_n = wid >> 2;
    const int m0 = blockIdx.y * BM;
    const int n0 = blockIdx.x * BN;

    const uint32_t aBh = smem_u32(sAh), aBl = smem_u32(sAl);
    const uint32_t bBh = smem_u32(sBh), bBl = smem_u32(sBl);

    float acc[2][NT][4];
    #pragma unroll
    for (int mt = 0; mt < 2; ++mt)
        #pragma unroll
        for (int nt = 0; nt < NT; ++nt)
            #pragma unroll
            for (int j = 0; j < 4; ++j) acc[mt][nt][j] = 0.f;

    // precomputed ldmatrix lane addressing
    const int a_row = (lane & 15);
    const int a_koff = (lane >> 4) << 3;
    const int b_row = ((lane >> 4) << 3) + (lane & 7);
    const int b_koff = ((lane >> 3) & 1) << 3;

    for (int k0 = 0; k0 < K; k0 += BK) {
        // ---- stage A tile (128 x 32 fp32 -> hi/lo bf16) ----
        #pragma unroll
        for (int i = 0; i < (BM*BK/4)/256; ++i) {
            int idx = tid + i*256;
            int m = idx >> 3, ks = (idx & 7) << 2;
            float4 v = *reinterpret_cast<const float4*>(A + (size_t)(m0+m)*lda + k0 + ks);
            float hx = __bfloat162float(__float2bfloat16(v.x));
            float hy = __bfloat162float(__float2bfloat16(v.y));
            float hz = __bfloat162float(__float2bfloat16(v.z));
            float hw = __bfloat162float(__float2bfloat16(v.w));
            int off = m*PITCH + ks;
            *reinterpret_cast<uint2*>(sAh + off) =
                make_uint2(pack_bf16x2(v.x, v.y), pack_bf16x2(v.z, v.w));
            *reinterpret_cast<uint2*>(sAl + off) =
                make_uint2(pack_bf16x2(v.x-hx, v.y-hy), pack_bf16x2(v.z-hz, v.w-hw));
        }
        // ---- stage B tile (BN x 32) ----
        #pragma unroll
        for (int i = 0; i < (BN*BK/4)/256; ++i) {
            int idx = tid + i*256;
            int n = idx >> 3, ks = (idx & 7) << 2;
            float4 v = *reinterpret_cast<const float4*>(Bm + (size_t)(n0+n)*ldb + k0 + ks);
            float hx = __bfloat162float(__float2bfloat16(v.x));
            float hy = __bfloat162float(__float2bfloat16(v.y));
            float hz = __bfloat162float(__float2bfloat16(v.z));
            float hw = __bfloat162float(__float2bfloat16(v.w));
            int off = n*PITCH + ks;
            *reinterpret_cast<uint2*>(sBh + off) =
                make_uint2(pack_bf16x2(v.x, v.y), pack_bf16x2(v.z, v.w));
            *reinterpret_cast<uint2*>(sBl + off) =
                make_uint2(pack_bf16x2(v.x-hx, v.y-hy), pack_bf16x2(v.z-hz, v.w-hw));
        }
        __syncthreads();

        #pragma unroll
        for (int kstep = 0; kstep < 2; ++kstep) {
            uint32_t aH[2][4], aL[2][4];
            #pragma unroll
            for (int mt = 0; mt < 2; ++mt) {
                uint32_t off = (uint32_t)(((warp_m*32 + mt*16 + a_row)*PITCH
                                          + kstep*16 + a_koff) * 2);
                ldsm4(aH[mt], aBh + off);
                ldsm4(aL[mt], aBl + off);
            }
            uint32_t bH[NT][2], bL[NT][2];
            #pragma unroll
            for (int p = 0; p < NT/2; ++p) {
                uint32_t off = (uint32_t)(((warp_n*WN + p*16 + b_row)*PITCH
                                          + kstep*16 + b_koff) * 2);
                uint32_t r[4];
                ldsm4(r, bBh + off);
                bH[2*p][0]=r[0]; bH[2*p][1]=r[1]; bH[2*p+1][0]=r[2]; bH[2*p+1][1]=r[3];
                ldsm4(r, bBl + off);
                bL[2*p][0]=r[0]; bL[2*p][1]=r[1]; bL[2*p+1][0]=r[2]; bL[2*p+1][1]=r[3];
            }
            #pragma unroll
            for (int mt = 0; mt < 2; ++mt)
                #pragma unroll
                for (int nt = 0; nt < NT; ++nt) {
                    mma_bf16(acc[mt][nt], aH[mt], bH[nt][0], bH[nt][1]);
                    mma_bf16(acc[mt][nt], aH[mt], bL[nt][0], bL[nt][1]);
                    mma_bf16(acc[mt][nt], aL[mt], bH[nt][0], bH[nt][1]);
                }
        }
        __syncthreads();
    }

    // ---- epilogue: direct fp32 stores ----
    #pragma unroll
    for (int mt = 0; mt < 2; ++mt) {
        int r0 = m0 + warp_m*32 + mt*16 + (lane >> 2);
        #pragma unroll
        for (int nt = 0; nt < NT; ++nt) {
            int c0 = n0 + warp_n*WN + nt*8 + ((lane & 3) << 1);
            *reinterpret_cast<float2*>(C + (size_t)r0*ldc + c0) =
                make_float2(acc[mt][nt][0], acc[mt][nt][1]);
            *reinterpret_cast<float2*>(C + (size_t)(r0+8)*ldc + c0) =
                make_float2(acc[mt][nt][2], acc[mt][nt][3]);
        }
    }
}

// ---------------- depthwise causal conv (kernel=4) + bias + silu --------------
__global__ void conv_silu_kernel(const float* __restrict__ conv_w,
                                 const float* __restrict__ conv_b)
{
    const int m = blockIdx.x;          // token index b*SEQ + l
    const int d = threadIdx.x;         // channel
    const int l = m & (SEQ - 1);
    float acc = conv_b[d];
    #pragma unroll
    for (int k = 0; k < DCONV; ++k) {
        int ll = l + k - (DCONV - 1);
        if (ll >= 0)
            acc = fmaf(conv_w[d*DCONV + k], g_xi[(m + k - (DCONV-1))*DINNER + d], acc);
    }
    g_xc[m*DINNER + d] = acc / (1.f + __expf(-acc)); // silu
}

// ---------------- z at the last token only: z = x[:, -1, :] @ W_in[1024:].T ---
__global__ void zlast_kernel(const float* __restrict__ x,
                             const float* __restrict__ W_in)
{
    const int warp = (blockIdx.x * blockDim.x + threadIdx.x) >> 5; // 0..8191
    const int lane = threadIdx.x & 31;
    const int b = warp >> 10;
    const int d = warp & (DINNER - 1);
    const float* xr = x + ((size_t)b*SEQ + (SEQ-1)) * DMODEL;
    const float* wr = W_in + (size_t)(DINNER + d) * DMODEL;
    float acc = 0.f;
    #pragma unroll 4
    for (int k = lane; k < DMODEL; k += 32) acc = fmaf(xr[k], wr[k], acc);
    #pragma unroll
    for (int off = 16; off; off >>= 1) acc += __shfl_down_sync(0xffffffffu, acc, off);
    if (lane == 0) g_zlast[warp] = acc;
}

// ---------------- selective scan with fused dt projection + softplus ----------
// block: 256 threads = 16 channels x 16 states, one batch b, channels dbase..+15
__global__ void scan_kernel(const float* __restrict__ A_log,
                            const float* __restrict__ Dv,
                            const float* __restrict__ W_dt,
                            const float* __restrict__ b_dt)
{
    const int b     = blockIdx.x >> 6;            // 512 blocks = 8 b * 64 d-groups
    const int dbase = (blockIdx.x & 63) << 4;
    const int tid = threadIdx.x;
    const int dl  = tid >> 4;                     // 0..15 local channel
    const int s   = tid & 15;                     // state
    const int d   = dbase + dl;

    __shared__ float s_wdt[16][33];
    __shared__ float s_bdt[16];
    __shared__ float s_r [64][32];
    __shared__ float s_dt[64][16];
    __shared__ float s_u [64][16];
    __shared__ float s_B [64][16];

    #pragma unroll
    for (int e = tid; e < 16*32; e += 256) {
        int c = e >> 5, r = e & 31;
        s_wdt[c][r] = W_dt[(dbase + c)*DTRANK + r];
    }
    if (tid < 16) s_bdt[tid] = b_dt[dbase + tid];

    const float A_s = -__expf(A_log[d*DSTATE + s]);
    float h = 0.f;

    for (int t0 = 0; t0 < SEQ; t0 += 64) {
        __syncthreads();
        #pragma unroll
        for (int i = 0; i < 8; ++i) {
            int idx = tid + i*256;                // dbc[:, :32]
            int tt = idx >> 5, r = idx & 31;
            s_r[tt][r] = g_dbc[(b*SEQ + t0 + tt)*NDBC + r];
        }
        #pragma unroll
        for (int i = 0; i < 4; ++i) {
            int idx = tid + i*256;
            int tt = idx >> 4, c = idx & 15;
            int m = b*SEQ + t0 + tt;
            s_u[tt][c] = g_xc [m*DINNER + dbase + c];
            s_B[tt][c] = g_dbc[m*NDBC + DTRANK + c];
        }
        __syncthreads();
        // dt = softplus(dbc[:, :32] @ W_dt^T + b_dt)
        #pragma unroll
        for (int i = 0; i < 4; ++i) {
            int idx = tid + i*256;
            int tt = idx >> 4, c = idx & 15;
            float acc = s_bdt[c];
            #pragma unroll
            for (int r = 0; r < 32; ++r)
                acc = fmaf(s_r[tt][r], s_wdt[c][r], acc);
            s_dt[tt][c] = (acc > 20.f) ? acc : log1pf(__expf(acc));
        }
        __syncthreads();
        #pragma unroll 8
        for (int tt = 0; tt < 64; ++tt) {
            float dtv = s_dt[tt][dl];
            h = fmaf(__expf(dtv * A_s), h, (dtv * s_u[tt][dl]) * s_B[tt][s]);
        }
    }

    const int mlast = b*SEQ + (SEQ-1);
    float y = h * g_dbc[mlast*NDBC + DTRANK + DSTATE + s];
    #pragma unroll
    for (int off = 8; off; off >>= 1) y += __shfl_down_sync(0xffffffffu, y, off, 16);
    if (s == 0) {
        float ul = g_xc[mlast*DINNER + d];
        float zl = g_zlast[b*DINNER + d];
        float silu_z = zl / (1.f + __expf(-zl));
        g_ylast[b*DINNER + d] = (y + Dv[d]*ul) * silu_z;
    }
}

// ---------------- tail: out proj (last token) + layernorm + head --------------
__global__ void final_kernel(const float* __restrict__ W_out,
                             const float* __restrict__ ln_g,
                             const float* __restrict__ ln_b,
                             const float* __restrict__ head_W,
                             const float* __restrict__ head_b,
                             float* __restrict__ out)
{
    const int b = blockIdx.x;
    const int j = threadIdx.x; // 512
    __shared__ float sy[DINNER];
    __shared__ float sn[DMODEL];
    __shared__ float rbuf[DMODEL];

    sy[j]         = g_ylast[b*DINNER + j];
    sy[j + 512]   = g_ylast[b*DINNER + 512 + j];
    __syncthreads();

    const float* wr = W_out + (size_t)j * DINNER;
    float a0 = 0.f, a1 = 0.f, a2 = 0.f, a3 = 0.f;
    #pragma unroll 4
    for (int k = 0; k < DINNER; k += 4) {
        float4 w = *reinterpret_cast<const float4*>(wr + k);
        a0 = fmaf(sy[k+0], w.x, a0);
        a1 = fmaf(sy[k+1], w.y, a1);
        a2 = fmaf(sy[k+2], w.z, a2);
        a3 = fmaf(sy[k+3], w.w, a3);
    }
    float last = (a0 + a1) + (a2 + a3);

    rbuf[j] = last;
    __syncthreads();
    #pragma unroll
    for (int st = 256; st > 0; st >>= 1) {
        if (j < st) rbuf[j] += rbuf[j + st];
        __syncthreads();
    }
    float mu = rbuf[0] / (float)DMODEL;
    __syncthreads();
    float diff = last - mu;
    rbuf[j] = diff * diff;
    __syncthreads();
    #pragma unroll
    for (int st = 256; st > 0; st >>= 1) {
        if (j < st) rbuf[j] += rbuf[j + st];
        __syncthreads();
    }
    float rstd = rsqrtf(rbuf[0] / (float)DMODEL + 1e-5f);
    __syncthreads();

    sn[j] = diff * rstd * ln_g[j] + ln_b[j];
    __syncthreads();

    const float* hw = head_W + (size_t)j * DMODEL;
    float h0 = 0.f, h1 = 0.f, h2 = 0.f, h3 = 0.f;
    #pragma unroll 4
    for (int k = 0; k < DMODEL; k += 4) {
        float4 w = *reinterpret_cast<const float4*>(hw + k);
        h0 = fmaf(sn[k+0], w.x, h0);
        h1 = fmaf(sn[k+1], w.y, h1);
        h2 = fmaf(sn[k+2], w.z, h2);
        h3 = fmaf(sn[k+3], w.w, h3);
    }
    out[b*DMODEL + j] = head_b[j] + (h0 + h1) + (h2 + h3);
}

// ---------------- launch --------------------------------------------------------
extern "C" void kernel_launch(void* const* d_in, const int* in_sizes, int n_in,
                              void* d_out, int out_size)
{
    const float* x      = (const float*)d_in[0];   // [8,1024,512]
    const float* W_in   = (const float*)d_in[1];   // [2048,512]
    const float* conv_w = (const float*)d_in[2];   // [1024,4]
    const float* conv_b = (const float*)d_in[3];   // [1024]
    const float* W_x    = (const float*)d_in[4];   // [64,1024]
    const float* W_dt   = (const float*)d_in[5];   // [1024,32]
    const float* b_dt   = (const float*)d_in[6];   // [1024]
    const float* A_log  = (const float*)d_in[7];   // [1024,16]
    const float* Dv     = (const float*)d_in[8];   // [1024]
    const float* W_out  = (const float*)d_in[9];   // [512,1024]
    const float* ln_g   = (const float*)d_in[10];  // [512]
    const float* ln_b   = (const float*)d_in[11];  // [512]
    const float* head_W = (const float*)d_in[12];  // [512,512]
    const float* head_b = (const float*)d_in[13];  // [512]
    float* out = (float*)d_out;                    // [8,512]

    float* xi  = nullptr; cudaGetSymbolAddress((void**)&xi,  g_xi);
    float* xc  = nullptr; cudaGetSymbolAddress((void**)&xc,  g_xc);
    float* dbc = nullptr; cudaGetSymbolAddress((void**)&dbc, g_dbc);

    // K1: xi = x @ W_in[:1024].T   (M=8192, N=1024, K=512) — HMMA hi/lo split
    gemm_mma<128><<<dim3(DINNER/128, MTOK/128), 256>>>(x, W_in, xi,
                                                       DMODEL, DMODEL, DMODEL, DINNER);
    // K2: depthwise conv + silu
    conv_silu_kernel<<<MTOK, DINNER>>>(conv_w, conv_b);

    // K3: dbc = xc @ W_x.T   (M=8192, N=64, K=1024) — HMMA hi/lo split
    // NOTE: BM=128 fixed -> grid.y must be MTOK/128 (round-3 crash was MTOK/64 here)
    gemm_mma<64><<<dim3(1, MTOK/128), 256>>>(xc, W_x, dbc,
                                             DINNER, DINNER, DINNER, NDBC);

    // K4: z at last token
    zlast_kernel<<<(BATCH*DINNER*32)/256, 256>>>(x, W_in);

    // K5: selective scan (final y only) with fused dt projection
    scan_kernel<<<BATCH * (DINNER/16), 256>>>(A_log, Dv, W_dt, b_dt);

    // K6: out projection (last token) + LN + head
    final_kernel<<<BATCH, DMODEL>>>(W_out, ln_g, ln_b, head_W, head_b, out);
}

// round 5
// speedup vs baseline: 1.9263x; 1.1177x over previous
#include <cuda_runtime.h>
#include <cuda_bf16.h>
#include <cstdint>

// Problem constants
#define BATCH   8
#define SEQ     1024
#define DMODEL  512
#define DINNER  1024
#define DSTATE  16
#define DTRANK  32
#define DCONV   4
#define MTOK    (BATCH*SEQ)          // 8192 tokens
#define NDBC    (DTRANK + 2*DSTATE)  // 64

// ---------------- scratch (static device globals; no allocation) -------------
__device__ float g_xi [MTOK * DINNER];   // pre-conv inner activations
__device__ float g_xc [MTOK * DINNER];   // post-conv silu activations (u)
__device__ float g_dbc[MTOK * NDBC];     // [dt_rank | B | C] projections
__device__ float g_zlast[BATCH * DINNER];
__device__ float g_ylast[BATCH * DINNER];
// pre-split bf16 hi/lo operands for K1
__device__ __nv_bfloat16 g_xh [MTOK * DMODEL];
__device__ __nv_bfloat16 g_xl [MTOK * DMODEL];
__device__ __nv_bfloat16 g_wih[DINNER * DMODEL];
__device__ __nv_bfloat16 g_wil[DINNER * DMODEL];

// ======================= warp-mma helpers (generic sm_80+) ===================
__device__ __forceinline__ uint32_t smem_u32(const void* p) {
    uint32_t a;
    asm("{ .reg .u64 t; cvta.to.shared.u64 t, %1; cvt.u32.u64 %0, t; }" : "=r"(a) : "l"(p));
    return a;
}
__device__ __forceinline__ void ldsm4(uint32_t* r, uint32_t addr) {
    asm volatile("ldmatrix.sync.aligned.m8n8.x4.shared.b16 {%0,%1,%2,%3}, [%4];"
                 : "=r"(r[0]), "=r"(r[1]), "=r"(r[2]), "=r"(r[3]) : "r"(addr));
}
__device__ __forceinline__ void mma_bf16(float* d, const uint32_t* a,
                                         uint32_t b0, uint32_t b1) {
    asm volatile("mma.sync.aligned.m16n8k16.row.col.f32.bf16.bf16.f32 "
                 "{%0,%1,%2,%3}, {%4,%5,%6,%7}, {%8,%9}, {%0,%1,%2,%3};"
                 : "+f"(d[0]), "+f"(d[1]), "+f"(d[2]), "+f"(d[3])
                 : "r"(a[0]), "r"(a[1]), "r"(a[2]), "r"(a[3]), "r"(b0), "r"(b1));
}
__device__ __forceinline__ uint32_t pack_bf16x2(float x, float y) {
    __nv_bfloat16 hx = __float2bfloat16(x), hy = __float2bfloat16(y);
    return ((uint32_t)__bfloat16_as_ushort(hy) << 16) | (uint32_t)__bfloat16_as_ushort(hx);
}
__device__ __forceinline__ void cp16(uint32_t dst, const void* src) {
    asm volatile("cp.async.cg.shared.global [%0], [%1], 16;" :: "r"(dst), "l"(src));
}
#define CP_COMMIT() asm volatile("cp.async.commit_group;" ::: "memory")
#define CP_WAIT1()  asm volatile("cp.async.wait_group 1;" ::: "memory")

// ---------------- fp32 -> bf16 hi/lo split (pre-pass for K1 operands) --------
__global__ void split_kernel(const float* __restrict__ src,
                             __nv_bfloat16* __restrict__ hi,
                             __nv_bfloat16* __restrict__ lo, int n4)
{
    int i = blockIdx.x * blockDim.x + threadIdx.x;
    if (i >= n4) return;
    float4 v = reinterpret_cast<const float4*>(src)[i];
    float hx = __bfloat162float(__float2bfloat16(v.x));
    float hy = __bfloat162float(__float2bfloat16(v.y));
    float hz = __bfloat162float(__float2bfloat16(v.z));
    float hw = __bfloat162float(__float2bfloat16(v.w));
    reinterpret_cast<uint2*>(hi)[i] =
        make_uint2(pack_bf16x2(v.x, v.y), pack_bf16x2(v.z, v.w));
    reinterpret_cast<uint2*>(lo)[i] =
        make_uint2(pack_bf16x2(v.x - hx, v.y - hy), pack_bf16x2(v.z - hz, v.w - hw));
}

// ====== K1: cp.async double-buffered bf16 split GEMM (pre-split operands) =====
// C[M,N] = (Ah+Al)[M,K] @ (Bh+Bl)[N,K]^T, 3-MMA split (drops lo*lo).
// Block 128x128, BK=32, 8 warps (4m x 2n), warp tile 32x64.
__global__ __launch_bounds__(256)
void gemm_bs(const __nv_bfloat16* __restrict__ Ah, const __nv_bfloat16* __restrict__ Al,
             const __nv_bfloat16* __restrict__ Bh, const __nv_bfloat16* __restrict__ Bl,
             float* __restrict__ C, int K, int lda, int ldb, int ldc)
{
    constexpr int BM = 128, BN = 128, BK = 32;
    constexpr int NT = 8;              // 8-wide n-tiles per warp (WN=64)
    constexpr int PITCH = BK + 8;      // 40 bf16 = 80B rows, 16B aligned
    constexpr int OFF_AH = 0;
    constexpr int OFF_AL = BM*PITCH;
    constexpr int OFF_BH = 2*BM*PITCH;
    constexpr int OFF_BL = 2*BM*PITCH + BN*PITCH;
    constexpr int STAGE  = 2*BM*PITCH + 2*BN*PITCH;   // bf16 elems per stage

    extern __shared__ __align__(16) uint16_t smem[];
    const uint32_t sbase = smem_u32(smem);

    const int tid  = threadIdx.x;
    const int wid  = tid >> 5;
    const int lane = tid & 31;
    const int warp_m = wid & 3;
    const int warp_n = wid >> 2;
    const int m0 = blockIdx.y * BM;
    const int n0 = blockIdx.x * BN;

    // staging decode: 2 iters of 256 threads cover 128 rows x 4 16B-segments
    const int ld_r = tid >> 2;             // row 0..63 (+64 on second iter)
    const int ld_c = (tid & 3) << 3;       // bf16 col 0,8,16,24

    float acc[2][NT][4];
    #pragma unroll
    for (int mt = 0; mt < 2; ++mt)
        #pragma unroll
        for (int nt = 0; nt < NT; ++nt)
            #pragma unroll
            for (int j = 0; j < 4; ++j) acc[mt][nt][j] = 0.f;

    // ldmatrix lane addressing
    const int a_row = (lane & 15);
    const int a_koff = (lane >> 4) << 3;
    const int b_row = ((lane >> 4) << 3) + (lane & 7);
    const int b_koff = ((lane >> 3) & 1) << 3;

    auto load_stage = [&](int s, int k0) {
        uint32_t base = sbase + (uint32_t)(s*STAGE*2);
        #pragma unroll
        for (int i = 0; i < 2; ++i) {
            int r = ld_r + i*64;
            uint32_t so = base + (uint32_t)((r*PITCH + ld_c)*2);
            const __nv_bfloat16* pa = Ah + (size_t)(m0+r)*lda + k0 + ld_c;
            const __nv_bfloat16* pl = Al + (size_t)(m0+r)*lda + k0 + ld_c;
            cp16(so + OFF_AH*2, pa);
            cp16(so + OFF_AL*2, pl);
            const __nv_bfloat16* pb = Bh + (size_t)(n0+r)*ldb + k0 + ld_c;
            const __nv_bfloat16* pbl = Bl + (size_t)(n0+r)*ldb + k0 + ld_c;
            cp16(so + OFF_BH*2, pb);
            cp16(so + OFF_BL*2, pbl);
        }
    };

    load_stage(0, 0);
    CP_COMMIT();

    int buf = 0;
    for (int k0 = 0; k0 < K; k0 += BK) {
        if (k0 + BK < K) load_stage(buf ^ 1, k0 + BK);
        CP_COMMIT();
        CP_WAIT1();
        __syncthreads();

        const uint32_t stg = sbase + (uint32_t)(buf*STAGE*2);
        #pragma unroll
        for (int kstep = 0; kstep < 2; ++kstep) {
            uint32_t aH[2][4], aL[2][4];
            #pragma unroll
            for (int mt = 0; mt < 2; ++mt) {
                uint32_t off = (uint32_t)(((warp_m*32 + mt*16 + a_row)*PITCH
                                          + kstep*16 + a_koff) * 2);
                ldsm4(aH[mt], stg + OFF_AH*2 + off);
                ldsm4(aL[mt], stg + OFF_AL*2 + off);
            }
            uint32_t bH[NT][2], bL[NT][2];
            #pragma unroll
            for (int p = 0; p < NT/2; ++p) {
                uint32_t off = (uint32_t)(((warp_n*64 + p*16 + b_row)*PITCH
                                          + kstep*16 + b_koff) * 2);
                uint32_t r[4];
                ldsm4(r, stg + OFF_BH*2 + off);
                bH[2*p][0]=r[0]; bH[2*p][1]=r[1]; bH[2*p+1][0]=r[2]; bH[2*p+1][1]=r[3];
                ldsm4(r, stg + OFF_BL*2 + off);
                bL[2*p][0]=r[0]; bL[2*p][1]=r[1]; bL[2*p+1][0]=r[2]; bL[2*p+1][1]=r[3];
            }
            #pragma unroll
            for (int mt = 0; mt < 2; ++mt)
                #pragma unroll
                for (int nt = 0; nt < NT; ++nt) {
                    mma_bf16(acc[mt][nt], aH[mt], bH[nt][0], bH[nt][1]);
                    mma_bf16(acc[mt][nt], aH[mt], bL[nt][0], bL[nt][1]);
                    mma_bf16(acc[mt][nt], aL[mt], bH[nt][0], bH[nt][1]);
                }
        }
        __syncthreads();
        buf ^= 1;
    }

    #pragma unroll
    for (int mt = 0; mt < 2; ++mt) {
        int r0 = m0 + warp_m*32 + mt*16 + (lane >> 2);
        #pragma unroll
        for (int nt = 0; nt < NT; ++nt) {
            int c0 = n0 + warp_n*64 + nt*8 + ((lane & 3) << 1);
            *reinterpret_cast<float2*>(C + (size_t)r0*ldc + c0) =
                make_float2(acc[mt][nt][0], acc[mt][nt][1]);
            *reinterpret_cast<float2*>(C + (size_t)(r0+8)*ldc + c0) =
                make_float2(acc[mt][nt][2], acc[mt][nt][3]);
        }
    }
}

// ============ K3: fp32-input split GEMM (reads each operand once) ============
template<int BN>
__global__ __launch_bounds__(256)
void gemm_mma(const float* __restrict__ A, const float* __restrict__ Bm,
              float* __restrict__ C, int K, int lda, int ldb, int ldc)
{
    constexpr int BM = 128, BK = 32;
    constexpr int WN = BN / 2;
    constexpr int NT = WN / 8;
    constexpr int PITCH = BK + 8;

    __shared__ __align__(16) uint16_t sAh[BM*PITCH], sAl[BM*PITCH];
    __shared__ __align__(16) uint16_t sBh[BN*PITCH], sBl[BN*PITCH];

    const int tid  = threadIdx.x;
    const int wid  = tid >> 5;
    const int lane = tid & 31;
    const int warp_m = wid & 3;
    const int warp_n = wid >> 2;
    const int m0 = blockIdx.y * BM;
    const int n0 = blockIdx.x * BN;

    const uint32_t aBh = smem_u32(sAh), aBl = smem_u32(sAl);
    const uint32_t bBh = smem_u32(sBh), bBl = smem_u32(sBl);

    float acc[2][NT][4];
    #pragma unroll
    for (int mt = 0; mt < 2; ++mt)
        #pragma unroll
        for (int nt = 0; nt < NT; ++nt)
            #pragma unroll
            for (int j = 0; j < 4; ++j) acc[mt][nt][j] = 0.f;

    const int a_row = (lane & 15);
    const int a_koff = (lane >> 4) << 3;
    const int b_row = ((lane >> 4) << 3) + (lane & 7);
    const int b_koff = ((lane >> 3) & 1) << 3;

    for (int k0 = 0; k0 < K; k0 += BK) {
        #pragma unroll
        for (int i = 0; i < (BM*BK/4)/256; ++i) {
            int idx = tid + i*256;
            int m = idx >> 3, ks = (idx & 7) << 2;
            float4 v = *reinterpret_cast<const float4*>(A + (size_t)(m0+m)*lda + k0 + ks);
            float hx = __bfloat162float(__float2bfloat16(v.x));
            float hy = __bfloat162float(__float2bfloat16(v.y));
            float hz = __bfloat162float(__float2bfloat16(v.z));
            float hw = __bfloat162float(__float2bfloat16(v.w));
            int off = m*PITCH + ks;
            *reinterpret_cast<uint2*>(sAh + off) =
                make_uint2(pack_bf16x2(v.x, v.y), pack_bf16x2(v.z, v.w));
            *reinterpret_cast<uint2*>(sAl + off) =
                make_uint2(pack_bf16x2(v.x-hx, v.y-hy), pack_bf16x2(v.z-hz, v.w-hw));
        }
        #pragma unroll
        for (int i = 0; i < (BN*BK/4)/256; ++i) {
            int idx = tid + i*256;
            int n = idx >> 3, ks = (idx & 7) << 2;
            float4 v = *reinterpret_cast<const float4*>(Bm + (size_t)(n0+n)*ldb + k0 + ks);
            float hx = __bfloat162float(__float2bfloat16(v.x));
            float hy = __bfloat162float(__float2bfloat16(v.y));
            float hz = __bfloat162float(__float2bfloat16(v.z));
            float hw = __bfloat162float(__float2bfloat16(v.w));
            int off = n*PITCH + ks;
            *reinterpret_cast<uint2*>(sBh + off) =
                make_uint2(pack_bf16x2(v.x, v.y), pack_bf16x2(v.z, v.w));
            *reinterpret_cast<uint2*>(sBl + off) =
                make_uint2(pack_bf16x2(v.x-hx, v.y-hy), pack_bf16x2(v.z-hz, v.w-hw));
        }
        __syncthreads();

        #pragma unroll
        for (int kstep = 0; kstep < 2; ++kstep) {
            uint32_t aH[2][4], aL[2][4];
            #pragma unroll
            for (int mt = 0; mt < 2; ++mt) {
                uint32_t off = (uint32_t)(((warp_m*32 + mt*16 + a_row)*PITCH
                                          + kstep*16 + a_koff) * 2);
                ldsm4(aH[mt], aBh + off);
                ldsm4(aL[mt], aBl + off);
            }
            uint32_t bH[NT][2], bL[NT][2];
            #pragma unroll
            for (int p = 0; p < NT/2; ++p) {
                uint32_t off = (uint32_t)(((warp_n*WN + p*16 + b_row)*PITCH
                                          + kstep*16 + b_koff) * 2);
                uint32_t r[4];
                ldsm4(r, bBh + off);
                bH[2*p][0]=r[0]; bH[2*p][1]=r[1]; bH[2*p+1][0]=r[2]; bH[2*p+1][1]=r[3];
                ldsm4(r, bBl + off);
                bL[2*p][0]=r[0]; bL[2*p][1]=r[1]; bL[2*p+1][0]=r[2]; bL[2*p+1][1]=r[3];
            }
            #pragma unroll
            for (int mt = 0; mt < 2; ++mt)
                #pragma unroll
                for (int nt = 0; nt < NT; ++nt) {
                    mma_bf16(acc[mt][nt], aH[mt], bH[nt][0], bH[nt][1]);
                    mma_bf16(acc[mt][nt], aH[mt], bL[nt][0], bL[nt][1]);
                    mma_bf16(acc[mt][nt], aL[mt], bH[nt][0], bH[nt][1]);
                }
        }
        __syncthreads();
    }

    #pragma unroll
    for (int mt = 0; mt < 2; ++mt) {
        int r0 = m0 + warp_m*32 + mt*16 + (lane >> 2);
        #pragma unroll
        for (int nt = 0; nt < NT; ++nt) {
            int c0 = n0 + warp_n*WN + nt*8 + ((lane & 3) << 1);
            *reinterpret_cast<float2*>(C + (size_t)r0*ldc + c0) =
                make_float2(acc[mt][nt][0], acc[mt][nt][1]);
            *reinterpret_cast<float2*>(C + (size_t)(r0+8)*ldc + c0) =
                make_float2(acc[mt][nt][2], acc[mt][nt][3]);
        }
    }
}

// ---------------- depthwise causal conv (kernel=4) + bias + silu --------------
__global__ void conv_silu_kernel(const float* __restrict__ conv_w,
                                 const float* __restrict__ conv_b)
{
    const int m = blockIdx.x;
    const int d = threadIdx.x;
    const int l = m & (SEQ - 1);
    float acc = conv_b[d];
    #pragma unroll
    for (int k = 0; k < DCONV; ++k) {
        int ll = l + k - (DCONV - 1);
        if (ll >= 0)
            acc = fmaf(conv_w[d*DCONV + k], g_xi[(m + k - (DCONV-1))*DINNER + d], acc);
    }
    g_xc[m*DINNER + d] = acc / (1.f + __expf(-acc));
}

// ---------------- z at the last token only -----------------------------------
__global__ void zlast_kernel(const float* __restrict__ x,
                             const float* __restrict__ W_in)
{
    const int warp = (blockIdx.x * blockDim.x + threadIdx.x) >> 5;
    const int lane = threadIdx.x & 31;
    const int b = warp >> 10;
    const int d = warp & (DINNER - 1);
    const float* xr = x + ((size_t)b*SEQ + (SEQ-1)) * DMODEL;
    const float* wr = W_in + (size_t)(DINNER + d) * DMODEL;
    float acc = 0.f;
    #pragma unroll 4
    for (int k = lane; k < DMODEL; k += 32) acc = fmaf(xr[k], wr[k], acc);
    #pragma unroll
    for (int off = 16; off; off >>= 1) acc += __shfl_down_sync(0xffffffffu, acc, off);
    if (lane == 0) g_zlast[warp] = acc;
}

// ---------------- selective scan with fused dt projection + softplus ----------
__global__ void scan_kernel(const float* __restrict__ A_log,
                            const float* __restrict__ Dv,
                            const float* __restrict__ W_dt,
                            const float* __restrict__ b_dt)
{
    const int b     = blockIdx.x >> 6;
    const int dbase = (blockIdx.x & 63) << 4;
    const int tid = threadIdx.x;
    const int dl  = tid >> 4;
    const int s   = tid & 15;
    const int d   = dbase + dl;

    __shared__ float s_wdt[16][33];
    __shared__ float s_bdt[16];
    __shared__ float s_r [64][32];
    __shared__ float s_dt[64][16];
    __shared__ float s_u [64][16];
    __shared__ float s_B [64][16];

    #pragma unroll
    for (int e = tid; e < 16*32; e += 256) {
        int c = e >> 5, r = e & 31;
        s_wdt[c][r] = W_dt[(dbase + c)*DTRANK + r];
    }
    if (tid < 16) s_bdt[tid] = b_dt[dbase + tid];

    const float A_s = -__expf(A_log[d*DSTATE + s]);
    float h = 0.f;

    for (int t0 = 0; t0 < SEQ; t0 += 64) {
        __syncthreads();
        #pragma unroll
        for (int i = 0; i < 8; ++i) {
            int idx = tid + i*256;
            int tt = idx >> 5, r = idx & 31;
            s_r[tt][r] = g_dbc[(b*SEQ + t0 + tt)*NDBC + r];
        }
        #pragma unroll
        for (int i = 0; i < 4; ++i) {
            int idx = tid + i*256;
            int tt = idx >> 4, c = idx & 15;
            int m = b*SEQ + t0 + tt;
            s_u[tt][c] = g_xc [m*DINNER + dbase + c];
            s_B[tt][c] = g_dbc[m*NDBC + DTRANK + c];
        }
        __syncthreads();
        #pragma unroll
        for (int i = 0; i < 4; ++i) {
            int idx = tid + i*256;
            int tt = idx >> 4, c = idx & 15;
            float acc = s_bdt[c];
            #pragma unroll
            for (int r = 0; r < 32; ++r)
                acc = fmaf(s_r[tt][r], s_wdt[c][r], acc);
            s_dt[tt][c] = (acc > 20.f) ? acc : log1pf(__expf(acc));
        }
        __syncthreads();
        #pragma unroll 8
        for (int tt = 0; tt < 64; ++tt) {
            float dtv = s_dt[tt][dl];
            h = fmaf(__expf(dtv * A_s), h, (dtv * s_u[tt][dl]) * s_B[tt][s]);
        }
    }

    const int mlast = b*SEQ + (SEQ-1);
    float y = h * g_dbc[mlast*NDBC + DTRANK + DSTATE + s];
    #pragma unroll
    for (int off = 8; off; off >>= 1) y += __shfl_down_sync(0xffffffffu, y, off, 16);
    if (s == 0) {
        float ul = g_xc[mlast*DINNER + d];
        float zl = g_zlast[b*DINNER + d];
        float silu_z = zl / (1.f + __expf(-zl));
        g_ylast[b*DINNER + d] = (y + Dv[d]*ul) * silu_z;
    }
}

// ---------------- tail: out proj (last token) + layernorm + head --------------
__global__ void final_kernel(const float* __restrict__ W_out,
                             const float* __restrict__ ln_g,
                             const float* __restrict__ ln_b,
                             const float* __restrict__ head_W,
                             const float* __restrict__ head_b,
                             float* __restrict__ out)
{
    const int b = blockIdx.x;
    const int j = threadIdx.x;
    __shared__ float sy[DINNER];
    __shared__ float sn[DMODEL];
    __shared__ float rbuf[DMODEL];

    sy[j]       = g_ylast[b*DINNER + j];
    sy[j + 512] = g_ylast[b*DINNER + 512 + j];
    __syncthreads();

    const float* wr = W_out + (size_t)j * DINNER;
    float a0 = 0.f, a1 = 0.f, a2 = 0.f, a3 = 0.f;
    #pragma unroll 4
    for (int k = 0; k < DINNER; k += 4) {
        float4 w = *reinterpret_cast<const float4*>(wr + k);
        a0 = fmaf(sy[k+0], w.x, a0);
        a1 = fmaf(sy[k+1], w.y, a1);
        a2 = fmaf(sy[k+2], w.z, a2);
        a3 = fmaf(sy[k+3], w.w, a3);
    }
    float last = (a0 + a1) + (a2 + a3);

    rbuf[j] = last;
    __syncthreads();
    #pragma unroll
    for (int st = 256; st > 0; st >>= 1) {
        if (j < st) rbuf[j] += rbuf[j + st];
        __syncthreads();
    }
    float mu = rbuf[0] / (float)DMODEL;
    __syncthreads();
    float diff = last - mu;
    rbuf[j] = diff * diff;
    __syncthreads();
    #pragma unroll
    for (int st = 256; st > 0; st >>= 1) {
        if (j < st) rbuf[j] += rbuf[j + st];
        __syncthreads();
    }
    float rstd = rsqrtf(rbuf[0] / (float)DMODEL + 1e-5f);
    __syncthreads();

    sn[j] = diff * rstd * ln_g[j] + ln_b[j];
    __syncthreads();

    const float* hw = head_W + (size_t)j * DMODEL;
    float h0 = 0.f, h1 = 0.f, h2 = 0.f, h3 = 0.f;
    #pragma unroll 4
    for (int k = 0; k < DMODEL; k += 4) {
        float4 w = *reinterpret_cast<const float4*>(hw + k);
        h0 = fmaf(sn[k+0], w.x, h0);
        h1 = fmaf(sn[k+1], w.y, h1);
        h2 = fmaf(sn[k+2], w.z, h2);
        h3 = fmaf(sn[k+3], w.w, h3);
    }
    out[b*DMODEL + j] = head_b[j] + (h0 + h1) + (h2 + h3);
}

// ---------------- launch --------------------------------------------------------
extern "C" void kernel_launch(void* const* d_in, const int* in_sizes, int n_in,
                              void* d_out, int out_size)
{
    const float* x      = (const float*)d_in[0];
    const float* W_in   = (const float*)d_in[1];
    const float* conv_w = (const float*)d_in[2];
    const float* conv_b = (const float*)d_in[3];
    const float* W_x    = (const float*)d_in[4];
    const float* W_dt   = (const float*)d_in[5];
    const float* b_dt   = (const float*)d_in[6];
    const float* A_log  = (const float*)d_in[7];
    const float* Dv     = (const float*)d_in[8];
    const float* W_out  = (const float*)d_in[9];
    const float* ln_g   = (const float*)d_in[10];
    const float* ln_b   = (const float*)d_in[11];
    const float* head_W = (const float*)d_in[12];
    const float* head_b = (const float*)d_in[13];
    float* out = (float*)d_out;

    float* xi  = nullptr; cudaGetSymbolAddress((void**)&xi,  g_xi);
    float* xc  = nullptr; cudaGetSymbolAddress((void**)&xc,  g_xc);
    float* dbc = nullptr; cudaGetSymbolAddress((void**)&dbc, g_dbc);
    __nv_bfloat16 *xh, *xl, *wih, *wil;
    cudaGetSymbolAddress((void**)&xh,  g_xh);
    cudaGetSymbolAddress((void**)&xl,  g_xl);
    cudaGetSymbolAddress((void**)&wih, g_wih);
    cudaGetSymbolAddress((void**)&wil, g_wil);

    // K0: split x and W_in[:1024] into bf16 hi/lo
    split_kernel<<<(MTOK*DMODEL/4 + 255)/256, 256>>>(x, xh, xl, MTOK*DMODEL/4);
    split_kernel<<<(DINNER*DMODEL/4 + 255)/256, 256>>>(W_in, wih, wil, DINNER*DMODEL/4);

    // K1: xi = x @ W_in[:1024].T — pre-split bf16, cp.async double-buffered
    {
        const int SMEM = (2*128*40 + 2*128*40) * 2 * 2;  // 81920 bytes
        cudaFuncSetAttribute(gemm_bs, cudaFuncAttributeMaxDynamicSharedMemorySize, SMEM);
        gemm_bs<<<dim3(DINNER/128, MTOK/128), 256, SMEM>>>(xh, xl, wih, wil, xi,
                                                           DMODEL, DMODEL, DMODEL, DINNER);
    }
    // K2: depthwise conv + silu
    conv_silu_kernel<<<MTOK, DINNER>>>(conv_w, conv_b);

    // K3: dbc = xc @ W_x.T  (reads each operand exactly once; in-kernel split)
    gemm_mma<64><<<dim3(1, MTOK/128), 256>>>(xc, W_x, dbc,
                                             DINNER, DINNER, DINNER, NDBC);

    // K4: z at last token
    zlast_kernel<<<(BATCH*DINNER*32)/256, 256>>>(x, W_in);

    // K5: selective scan (final y only) with fused dt projection
    scan_kernel<<<BATCH * (DINNER/16), 256>>>(A_log, Dv, W_dt, b_dt);

    // K6: out projection (last token) + LN + head
    final_kernel<<<BATCH, DMODEL>>>(W_out, ln_g, ln_b, head_W, head_b, out);
}

// round 6
// speedup vs baseline: 2.0600x; 1.0694x over previous
#include <cuda_runtime.h>
#include <cuda_bf16.h>
#include <cstdint>

#define BATCH   8
#define SEQ     1024
#define DMODEL  512
#define DINNER  1024
#define DSTATE  16
#define DTRANK  32
#define DCONV   4
#define MTOK    (BATCH*SEQ)
#define NDBC    (DTRANK + 2*DSTATE)

// ---------------- scratch -----------------------------------------------------
__device__ float g_xi [MTOK * DINNER];
__device__ float g_xc [MTOK * DINNER];
__device__ float g_dbc [MTOK * NDBC];
__device__ float g_dbc2[MTOK * NDBC];
__device__ float g_zlast[BATCH * DINNER];
__device__ float g_ylast[BATCH * DINNER];
__device__ __nv_bfloat16 g_xh [MTOK * DMODEL];
__device__ __nv_bfloat16 g_xl [MTOK * DMODEL];
__device__ __nv_bfloat16 g_wih[DINNER * DMODEL];
__device__ __nv_bfloat16 g_wil[DINNER * DMODEL];
__device__ __nv_bfloat16 g_wxh[NDBC * DINNER];
__device__ __nv_bfloat16 g_wxl[NDBC * DINNER];
__device__ __nv_bfloat16 g_xch[MTOK * DINNER];
__device__ __nv_bfloat16 g_xcl[MTOK * DINNER];

// ======================= warp-mma helpers ====================================
__device__ __forceinline__ uint32_t smem_u32(const void* p) {
    uint32_t a;
    asm("{ .reg .u64 t; cvta.to.shared.u64 t, %1; cvt.u32.u64 %0, t; }" : "=r"(a) : "l"(p));
    return a;
}
__device__ __forceinline__ void ldsm4(uint32_t* r, uint32_t addr) {
    asm volatile("ldmatrix.sync.aligned.m8n8.x4.shared.b16 {%0,%1,%2,%3}, [%4];"
                 : "=r"(r[0]), "=r"(r[1]), "=r"(r[2]), "=r"(r[3]) : "r"(addr));
}
__device__ __forceinline__ void mma_bf16(float* d, const uint32_t* a,
                                         uint32_t b0, uint32_t b1) {
    asm volatile("mma.sync.aligned.m16n8k16.row.col.f32.bf16.bf16.f32 "
                 "{%0,%1,%2,%3}, {%4,%5,%6,%7}, {%8,%9}, {%0,%1,%2,%3};"
                 : "+f"(d[0]), "+f"(d[1]), "+f"(d[2]), "+f"(d[3])
                 : "r"(a[0]), "r"(a[1]), "r"(a[2]), "r"(a[3]), "r"(b0), "r"(b1));
}
__device__ __forceinline__ uint32_t pack_bf16x2(float x, float y) {
    __nv_bfloat16 hx = __float2bfloat16(x), hy = __float2bfloat16(y);
    return ((uint32_t)__bfloat16_as_ushort(hy) << 16) | (uint32_t)__bfloat16_as_ushort(hx);
}
__device__ __forceinline__ void cp16(uint32_t dst, const void* src) {
    asm volatile("cp.async.cg.shared.global [%0], [%1], 16;" :: "r"(dst), "l"(src));
}
#define CP_COMMIT() asm volatile("cp.async.commit_group;" ::: "memory")
#define CP_WAIT1()  asm volatile("cp.async.wait_group 1;" ::: "memory")

// ---------------- fp32 -> bf16 hi/lo split ------------------------------------
__global__ void split_kernel(const float* __restrict__ src,
                             __nv_bfloat16* __restrict__ hi,
                             __nv_bfloat16* __restrict__ lo, int n4)
{
    int i = blockIdx.x * blockDim.x + threadIdx.x;
    if (i >= n4) return;
    float4 v = reinterpret_cast<const float4*>(src)[i];
    float hx = __bfloat162float(__float2bfloat16(v.x));
    float hy = __bfloat162float(__float2bfloat16(v.y));
    float hz = __bfloat162float(__float2bfloat16(v.z));
    float hw = __bfloat162float(__float2bfloat16(v.w));
    reinterpret_cast<uint2*>(hi)[i] =
        make_uint2(pack_bf16x2(v.x, v.y), pack_bf16x2(v.z, v.w));
    reinterpret_cast<uint2*>(lo)[i] =
        make_uint2(pack_bf16x2(v.x - hx, v.y - hy), pack_bf16x2(v.z - hz, v.w - hw));
}

// ====== pipelined bf16 split GEMM (pre-split operands, 3-MMA ≈ fp32) ==========
// C[M,N] = (Ah+Al)[M,K] @ (Bh+Bl)[N,K]^T.  Block 128 x BN, BK=32, 2-stage cp.async.
// gridDim.z splits K: block z handles [z*kspan, (z+1)*kspan), writes C0/C1.
template<int BN>
__global__ __launch_bounds__(256)
void gemm_bs(const __nv_bfloat16* __restrict__ Ah, const __nv_bfloat16* __restrict__ Al,
             const __nv_bfloat16* __restrict__ Bh, const __nv_bfloat16* __restrict__ Bl,
             float* __restrict__ C0, float* __restrict__ C1,
             int kspan, int lda, int ldb, int ldc)
{
    constexpr int BM = 128, BK = 32;
    constexpr int WN = BN / 2;
    constexpr int NT = WN / 8;
    constexpr int PITCH = BK + 8;
    constexpr int OFF_AH = 0;
    constexpr int OFF_AL = BM*PITCH;
    constexpr int OFF_BH = 2*BM*PITCH;
    constexpr int OFF_BL = 2*BM*PITCH + BN*PITCH;
    constexpr int STAGE  = 2*BM*PITCH + 2*BN*PITCH;

    extern __shared__ __align__(16) uint16_t smem[];
    const uint32_t sbase = smem_u32(smem);

    const int tid  = threadIdx.x;
    const int wid  = tid >> 5;
    const int lane = tid & 31;
    const int warp_m = wid & 3;
    const int warp_n = wid >> 2;
    const int m0 = blockIdx.y * BM;
    const int n0 = blockIdx.x * BN;
    const int kbeg = blockIdx.z * kspan;
    const int kend = kbeg + kspan;
    float* C = (blockIdx.z == 0) ? C0 : C1;

    const int ld_r = tid >> 2;
    const int ld_c = (tid & 3) << 3;

    float acc[2][NT][4];
    #pragma unroll
    for (int mt = 0; mt < 2; ++mt)
        #pragma unroll
        for (int nt = 0; nt < NT; ++nt)
            #pragma unroll
            for (int j = 0; j < 4; ++j) acc[mt][nt][j] = 0.f;

    const int a_row = (lane & 15);
    const int a_koff = (lane >> 4) << 3;
    const int b_row = ((lane >> 4) << 3) + (lane & 7);
    const int b_koff = ((lane >> 3) & 1) << 3;

    auto load_stage = [&](int s, int k0) {
        uint32_t base = sbase + (uint32_t)(s*STAGE*2);
        #pragma unroll
        for (int i = 0; i < 2; ++i) {
            int r = ld_r + i*64;
            uint32_t so = base + (uint32_t)((r*PITCH + ld_c)*2);
            cp16(so + OFF_AH*2, Ah + (size_t)(m0+r)*lda + k0 + ld_c);
            cp16(so + OFF_AL*2, Al + (size_t)(m0+r)*lda + k0 + ld_c);
            if (i*64 < BN) {
                cp16(so + OFF_BH*2, Bh + (size_t)(n0+r)*ldb + k0 + ld_c);
                cp16(so + OFF_BL*2, Bl + (size_t)(n0+r)*ldb + k0 + ld_c);
            }
        }
    };

    load_stage(0, kbeg);
    CP_COMMIT();

    int buf = 0;
    for (int k0 = kbeg; k0 < kend; k0 += BK) {
        if (k0 + BK < kend) load_stage(buf ^ 1, k0 + BK);
        CP_COMMIT();
        CP_WAIT1();
        __syncthreads();

        const uint32_t stg = sbase + (uint32_t)(buf*STAGE*2);
        #pragma unroll
        for (int kstep = 0; kstep < 2; ++kstep) {
            uint32_t aH[2][4], aL[2][4];
            #pragma unroll
            for (int mt = 0; mt < 2; ++mt) {
                uint32_t off = (uint32_t)(((warp_m*32 + mt*16 + a_row)*PITCH
                                          + kstep*16 + a_koff) * 2);
                ldsm4(aH[mt], stg + OFF_AH*2 + off);
                ldsm4(aL[mt], stg + OFF_AL*2 + off);
            }
            uint32_t bH[NT][2], bL[NT][2];
            #pragma unroll
            for (int p = 0; p < NT/2; ++p) {
                uint32_t off = (uint32_t)(((warp_n*WN + p*16 + b_row)*PITCH
                                          + kstep*16 + b_koff) * 2);
                uint32_t r[4];
                ldsm4(r, stg + OFF_BH*2 + off);
                bH[2*p][0]=r[0]; bH[2*p][1]=r[1]; bH[2*p+1][0]=r[2]; bH[2*p+1][1]=r[3];
                ldsm4(r, stg + OFF_BL*2 + off);
                bL[2*p][0]=r[0]; bL[2*p][1]=r[1]; bL[2*p+1][0]=r[2]; bL[2*p+1][1]=r[3];
            }
            #pragma unroll
            for (int mt = 0; mt < 2; ++mt)
                #pragma unroll
                for (int nt = 0; nt < NT; ++nt) {
                    mma_bf16(acc[mt][nt], aH[mt], bH[nt][0], bH[nt][1]);
                    mma_bf16(acc[mt][nt], aH[mt], bL[nt][0], bL[nt][1]);
                    mma_bf16(acc[mt][nt], aL[mt], bH[nt][0], bH[nt][1]);
                }
        }
        __syncthreads();
        buf ^= 1;
    }

    #pragma unroll
    for (int mt = 0; mt < 2; ++mt) {
        int r0 = m0 + warp_m*32 + mt*16 + (lane >> 2);
        #pragma unroll
        for (int nt = 0; nt < NT; ++nt) {
            int c0 = n0 + warp_n*WN + nt*8 + ((lane & 3) << 1);
            *reinterpret_cast<float2*>(C + (size_t)r0*ldc + c0) =
                make_float2(acc[mt][nt][0], acc[mt][nt][1]);
            *reinterpret_cast<float2*>(C + (size_t)(r0+8)*ldc + c0) =
                make_float2(acc[mt][nt][2], acc[mt][nt][3]);
        }
    }
}

// ---------------- add K-split halves of dbc ----------------------------------
__global__ void add_kernel(int n4)
{
    int i = blockIdx.x * blockDim.x + threadIdx.x;
    if (i >= n4) return;
    float4 a = reinterpret_cast<float4*>(g_dbc)[i];
    float4 b = reinterpret_cast<float4*>(g_dbc2)[i];
    reinterpret_cast<float4*>(g_dbc)[i] =
        make_float4(a.x+b.x, a.y+b.y, a.z+b.z, a.w+b.w);
}

// ---------- conv+silu, streaming (each xi element read once) -----------------
// grid (32 chunks, 8 batch); 256 threads, thread owns 4 channels; 32 tokens/blk
__global__ __launch_bounds__(256)
void conv_silu_kernel(const float* __restrict__ conv_w,
                      const float* __restrict__ conv_b)
{
    const int b  = blockIdx.y;
    const int t0 = blockIdx.x << 5;
    const int tid = threadIdx.x;
    const int d4 = tid << 2;

    float4 cw[4];
    #pragma unroll
    for (int j = 0; j < 4; ++j)
        cw[j] = reinterpret_cast<const float4*>(conv_w)[d4 + j]; // taps for ch d4+j
    const float4 bb = reinterpret_cast<const float4*>(conv_b)[tid];

    const float* src = g_xi + (size_t)(b*SEQ)*DINNER + d4;
    float4 x0, x1, x2;
    const float4 z4 = make_float4(0.f,0.f,0.f,0.f);
    x0 = (t0 >= 3) ? *reinterpret_cast<const float4*>(src + (size_t)(t0-3)*DINNER) : z4;
    x1 = (t0 >= 2) ? *reinterpret_cast<const float4*>(src + (size_t)(t0-2)*DINNER) : z4;
    x2 = (t0 >= 1) ? *reinterpret_cast<const float4*>(src + (size_t)(t0-1)*DINNER) : z4;

    #pragma unroll 4
    for (int l = t0; l < t0 + 32; ++l) {
        float4 x3 = *reinterpret_cast<const float4*>(src + (size_t)l*DINNER);
        float4 acc;
        acc.x = bb.x + cw[0].x*x0.x + cw[0].y*x1.x + cw[0].z*x2.x + cw[0].w*x3.x;
        acc.y = bb.y + cw[1].x*x0.y + cw[1].y*x1.y + cw[1].z*x2.y + cw[1].w*x3.y;
        acc.z = bb.z + cw[2].x*x0.z + cw[2].y*x1.z + cw[2].z*x2.z + cw[2].w*x3.z;
        acc.w = bb.w + cw[3].x*x0.w + cw[3].y*x1.w + cw[3].z*x2.w + cw[3].w*x3.w;
        acc.x = acc.x / (1.f + __expf(-acc.x));
        acc.y = acc.y / (1.f + __expf(-acc.y));
        acc.z = acc.z / (1.f + __expf(-acc.z));
        acc.w = acc.w / (1.f + __expf(-acc.w));

        size_t o = (size_t)(b*SEQ + l)*DINNER + d4;
        *reinterpret_cast<float4*>(g_xc + o) = acc;
        float hx = __bfloat162float(__float2bfloat16(acc.x));
        float hy = __bfloat162float(__float2bfloat16(acc.y));
        float hz = __bfloat162float(__float2bfloat16(acc.z));
        float hw = __bfloat162float(__float2bfloat16(acc.w));
        *reinterpret_cast<uint2*>(g_xch + o) =
            make_uint2(pack_bf16x2(acc.x, acc.y), pack_bf16x2(acc.z, acc.w));
        *reinterpret_cast<uint2*>(g_xcl + o) =
            make_uint2(pack_bf16x2(acc.x-hx, acc.y-hy), pack_bf16x2(acc.z-hz, acc.w-hw));
        x0 = x1; x1 = x2; x2 = x3;
    }
}

// ---------------- z at the last token only -----------------------------------
__global__ void zlast_kernel(const float* __restrict__ x,
                             const float* __restrict__ W_in)
{
    const int warp = (blockIdx.x * blockDim.x + threadIdx.x) >> 5;
    const int lane = threadIdx.x & 31;
    const int b = warp >> 10;
    const int d = warp & (DINNER - 1);
    const float* xr = x + ((size_t)b*SEQ + (SEQ-1)) * DMODEL;
    const float* wr = W_in + (size_t)(DINNER + d) * DMODEL;
    float acc = 0.f;
    #pragma unroll 4
    for (int k = lane; k < DMODEL; k += 32) acc = fmaf(xr[k], wr[k], acc);
    #pragma unroll
    for (int off = 16; off; off >>= 1) acc += __shfl_down_sync(0xffffffffu, acc, off);
    if (lane == 0) g_zlast[warp] = acc;
}

// ---------------- selective scan with fused dt projection ---------------------
__global__ void scan_kernel(const float* __restrict__ A_log,
                            const float* __restrict__ Dv,
                            const float* __restrict__ W_dt,
                            const float* __restrict__ b_dt)
{
    const int b     = blockIdx.x >> 6;
    const int dbase = (blockIdx.x & 63) << 4;
    const int tid = threadIdx.x;
    const int dl  = tid >> 4;
    const int s   = tid & 15;
    const int d   = dbase + dl;

    __shared__ float s_wdt[16][33];
    __shared__ float s_bdt[16];
    __shared__ float s_r [64][32];
    __shared__ float s_dt[64][16];
    __shared__ float s_u [64][16];
    __shared__ float s_B [64][16];

    #pragma unroll
    for (int e = tid; e < 16*32; e += 256) {
        int c = e >> 5, r = e & 31;
        s_wdt[c][r] = W_dt[(dbase + c)*DTRANK + r];
    }
    if (tid < 16) s_bdt[tid] = b_dt[dbase + tid];

    const float A_s = -__expf(A_log[d*DSTATE + s]);
    float h = 0.f;

    for (int t0 = 0; t0 < SEQ; t0 += 64) {
        __syncthreads();
        #pragma unroll
        for (int i = 0; i < 8; ++i) {
            int idx = tid + i*256;
            int tt = idx >> 5, r = idx & 31;
            s_r[tt][r] = g_dbc[(b*SEQ + t0 + tt)*NDBC + r];
        }
        #pragma unroll
        for (int i = 0; i < 4; ++i) {
            int idx = tid + i*256;
            int tt = idx >> 4, c = idx & 15;
            int m = b*SEQ + t0 + tt;
            s_u[tt][c] = g_xc [m*DINNER + dbase + c];
            s_B[tt][c] = g_dbc[m*NDBC + DTRANK + c];
        }
        __syncthreads();
        #pragma unroll
        for (int i = 0; i < 4; ++i) {
            int idx = tid + i*256;
            int tt = idx >> 4, c = idx & 15;
            float acc = s_bdt[c];
            #pragma unroll
            for (int r = 0; r < 32; ++r)
                acc = fmaf(s_r[tt][r], s_wdt[c][r], acc);
            s_dt[tt][c] = (acc > 20.f) ? acc : log1pf(__expf(acc));
        }
        __syncthreads();
        #pragma unroll 8
        for (int tt = 0; tt < 64; ++tt) {
            float dtv = s_dt[tt][dl];
            h = fmaf(__expf(dtv * A_s), h, (dtv * s_u[tt][dl]) * s_B[tt][s]);
        }
    }

    const int mlast = b*SEQ + (SEQ-1);
    float y = h * g_dbc[mlast*NDBC + DTRANK + DSTATE + s];
    #pragma unroll
    for (int off = 8; off; off >>= 1) y += __shfl_down_sync(0xffffffffu, y, off, 16);
    if (s == 0) {
        float ul = g_xc[mlast*DINNER + d];
        float zl = g_zlast[b*DINNER + d];
        float silu_z = zl / (1.f + __expf(-zl));
        g_ylast[b*DINNER + d] = (y + Dv[d]*ul) * silu_z;
    }
}

// ---------------- tail: out proj + LN + head ----------------------------------
__global__ void final_kernel(const float* __restrict__ W_out,
                             const float* __restrict__ ln_g,
                             const float* __restrict__ ln_b,
                             const float* __restrict__ head_W,
                             const float* __restrict__ head_b,
                             float* __restrict__ out)
{
    const int b = blockIdx.x;
    const int j = threadIdx.x;
    __shared__ float sy[DINNER];
    __shared__ float sn[DMODEL];
    __shared__ float rbuf[DMODEL];

    sy[j]       = g_ylast[b*DINNER + j];
    sy[j + 512] = g_ylast[b*DINNER + 512 + j];
    __syncthreads();

    const float* wr = W_out + (size_t)j * DINNER;
    float a0 = 0.f, a1 = 0.f, a2 = 0.f, a3 = 0.f;
    #pragma unroll 4
    for (int k = 0; k < DINNER; k += 4) {
        float4 w = *reinterpret_cast<const float4*>(wr + k);
        a0 = fmaf(sy[k+0], w.x, a0);
        a1 = fmaf(sy[k+1], w.y, a1);
        a2 = fmaf(sy[k+2], w.z, a2);
        a3 = fmaf(sy[k+3], w.w, a3);
    }
    float last = (a0 + a1) + (a2 + a3);

    rbuf[j] = last;
    __syncthreads();
    #pragma unroll
    for (int st = 256; st > 0; st >>= 1) {
        if (j < st) rbuf[j] += rbuf[j + st];
        __syncthreads();
    }
    float mu = rbuf[0] / (float)DMODEL;
    __syncthreads();
    float diff = last - mu;
    rbuf[j] = diff * diff;
    __syncthreads();
    #pragma unroll
    for (int st = 256; st > 0; st >>= 1) {
        if (j < st) rbuf[j] += rbuf[j + st];
        __syncthreads();
    }
    float rstd = rsqrtf(rbuf[0] / (float)DMODEL + 1e-5f);
    __syncthreads();

    sn[j] = diff * rstd * ln_g[j] + ln_b[j];
    __syncthreads();

    const float* hw = head_W + (size_t)j * DMODEL;
    float h0 = 0.f, h1 = 0.f, h2 = 0.f, h3 = 0.f;
    #pragma unroll 4
    for (int k = 0; k < DMODEL; k += 4) {
        float4 w = *reinterpret_cast<const float4*>(hw + k);
        h0 = fmaf(sn[k+0], w.x, h0);
        h1 = fmaf(sn[k+1], w.y, h1);
        h2 = fmaf(sn[k+2], w.z, h2);
        h3 = fmaf(sn[k+3], w.w, h3);
    }
    out[b*DMODEL + j] = head_b[j] + (h0 + h1) + (h2 + h3);
}

// ---------------- launch --------------------------------------------------------
extern "C" void kernel_launch(void* const* d_in, const int* in_sizes, int n_in,
                              void* d_out, int out_size)
{
    const float* x      = (const float*)d_in[0];
    const float* W_in   = (const float*)d_in[1];
    const float* conv_w = (const float*)d_in[2];
    const float* conv_b = (const float*)d_in[3];
    const float* W_x    = (const float*)d_in[4];
    const float* W_dt   = (const float*)d_in[5];
    const float* b_dt   = (const float*)d_in[6];
    const float* A_log  = (const float*)d_in[7];
    const float* Dv     = (const float*)d_in[8];
    const float* W_out  = (const float*)d_in[9];
    const float* ln_g   = (const float*)d_in[10];
    const float* ln_b   = (const float*)d_in[11];
    const float* head_W = (const float*)d_in[12];
    const float* head_b = (const float*)d_in[13];
    float* out = (float*)d_out;

    float *xi, *xc, *dbc, *dbc2;
    cudaGetSymbolAddress((void**)&xi,   g_xi);
    cudaGetSymbolAddress((void**)&xc,   g_xc);
    cudaGetSymbolAddress((void**)&dbc,  g_dbc);
    cudaGetSymbolAddress((void**)&dbc2, g_dbc2);
    __nv_bfloat16 *xh, *xl, *wih, *wil, *wxh, *wxl, *xch, *xcl;
    cudaGetSymbolAddress((void**)&xh,  g_xh);
    cudaGetSymbolAddress((void**)&xl,  g_xl);
    cudaGetSymbolAddress((void**)&wih, g_wih);
    cudaGetSymbolAddress((void**)&wil, g_wil);
    cudaGetSymbolAddress((void**)&wxh, g_wxh);
    cudaGetSymbolAddress((void**)&wxl, g_wxl);
    cudaGetSymbolAddress((void**)&xch, g_xch);
    cudaGetSymbolAddress((void**)&xcl, g_xcl);

    const int SMEM128 = (2*128*40 + 2*128*40) * 2 * 2;  // 81920
    const int SMEM64  = (2*128*40 + 2*64*40)  * 2 * 2;  // 61440
    cudaFuncSetAttribute(gemm_bs<128>, cudaFuncAttributeMaxDynamicSharedMemorySize, SMEM128);
    cudaFuncSetAttribute(gemm_bs<64>,  cudaFuncAttributeMaxDynamicSharedMemorySize, SMEM64);

    // launches 1-5 (so that gemm_bs<128> is launch #6 for ncu -s 5)
    const int half4 = MTOK*DMODEL/8;   // x split in two halves
    split_kernel<<<(half4 + 255)/256, 256>>>(x, xh, xl, half4);
    split_kernel<<<(half4 + 255)/256, 256>>>(x + (size_t)half4*4, xh + (size_t)half4*4,
                                             xl + (size_t)half4*4, half4);
    split_kernel<<<(DINNER*DMODEL/4 + 255)/256, 256>>>(W_in, wih, wil, DINNER*DMODEL/4);
    split_kernel<<<(NDBC*DINNER/4 + 255)/256, 256>>>(W_x, wxh, wxl, NDBC*DINNER/4);
    zlast_kernel<<<(BATCH*DINNER*32)/256, 256>>>(x, W_in);

    // K1 (#6): xi = x @ W_in[:1024].T
    gemm_bs<128><<<dim3(DINNER/128, MTOK/128, 1), 256, SMEM128>>>(
        xh, xl, wih, wil, xi, xi, DMODEL, DMODEL, DMODEL, DINNER);

    // conv + silu (+ bf16 hi/lo emit for K3)
    conv_silu_kernel<<<dim3(32, 8), 256>>>(conv_w, conv_b);

    // K3: dbc = xc @ W_x.T, K split in 2 (z-dim), 128 blocks
    gemm_bs<64><<<dim3(1, MTOK/128, 2), 256, SMEM64>>>(
        xch, xcl, wxh, wxl, dbc, dbc2, DINNER/2, DINNER, DINNER, NDBC);
    add_kernel<<<(MTOK*NDBC/4 + 255)/256, 256>>>(MTOK*NDBC/4);

    // scan + tail
    scan_kernel<<<BATCH * (DINNER/16), 256>>>(A_log, Dv, W_dt, b_dt);
    final_kernel<<<BATCH, DMODEL>>>(W_out, ln_g, ln_b, head_W, head_b, out);
}

// round 7
// speedup vs baseline: 2.0867x; 1.0130x over previous
#include <cuda_runtime.h>
#include <cuda_bf16.h>
#include <cstdint>

#define BATCH   8
#define SEQ     1024
#define DMODEL  512
#define DINNER  1024
#define DSTATE  16
#define DTRANK  32
#define DCONV   4
#define MTOK    (BATCH*SEQ)
#define NDBC    (DTRANK + 2*DSTATE)

// ---------------- scratch -----------------------------------------------------
__device__ float g_xi [MTOK * DINNER];
__device__ float g_xc [MTOK * DINNER];
__device__ float g_dbc [MTOK * NDBC];
__device__ float g_dbc2[MTOK * NDBC];
__device__ float g_zlast[BATCH * DINNER];
__device__ float g_ylast[BATCH * DINNER];
__device__ __nv_bfloat16 g_xh [MTOK * DMODEL];
__device__ __nv_bfloat16 g_xl [MTOK * DMODEL];
__device__ __nv_bfloat16 g_wih[DINNER * DMODEL];
__device__ __nv_bfloat16 g_wil[DINNER * DMODEL];
__device__ __nv_bfloat16 g_wxh[NDBC * DINNER];
__device__ __nv_bfloat16 g_wxl[NDBC * DINNER];
__device__ __nv_bfloat16 g_xch[MTOK * DINNER];
__device__ __nv_bfloat16 g_xcl[MTOK * DINNER];

// ======================= warp-mma helpers ====================================
__device__ __forceinline__ uint32_t smem_u32(const void* p) {
    uint32_t a;
    asm("{ .reg .u64 t; cvta.to.shared.u64 t, %1; cvt.u32.u64 %0, t; }" : "=r"(a) : "l"(p));
    return a;
}
__device__ __forceinline__ void ldsm4(uint32_t* r, uint32_t addr) {
    asm volatile("ldmatrix.sync.aligned.m8n8.x4.shared.b16 {%0,%1,%2,%3}, [%4];"
                 : "=r"(r[0]), "=r"(r[1]), "=r"(r[2]), "=r"(r[3]) : "r"(addr));
}
__device__ __forceinline__ void mma_bf16(float* d, const uint32_t* a,
                                         uint32_t b0, uint32_t b1) {
    asm volatile("mma.sync.aligned.m16n8k16.row.col.f32.bf16.bf16.f32 "
                 "{%0,%1,%2,%3}, {%4,%5,%6,%7}, {%8,%9}, {%0,%1,%2,%3};"
                 : "+f"(d[0]), "+f"(d[1]), "+f"(d[2]), "+f"(d[3])
                 : "r"(a[0]), "r"(a[1]), "r"(a[2]), "r"(a[3]), "r"(b0), "r"(b1));
}
__device__ __forceinline__ uint32_t pack_bf16x2(float x, float y) {
    __nv_bfloat16 hx = __float2bfloat16(x), hy = __float2bfloat16(y);
    return ((uint32_t)__bfloat16_as_ushort(hy) << 16) | (uint32_t)__bfloat16_as_ushort(hx);
}
__device__ __forceinline__ void cp16(uint32_t dst, const void* src) {
    asm volatile("cp.async.cg.shared.global [%0], [%1], 16;" :: "r"(dst), "l"(src));
}
#define CP_COMMIT() asm volatile("cp.async.commit_group;" ::: "memory")
#define CP_WAIT1()  asm volatile("cp.async.wait_group 1;" ::: "memory")

// ---------------- fp32 -> bf16 hi/lo split ------------------------------------
__global__ void split_kernel(const float* __restrict__ src,
                             __nv_bfloat16* __restrict__ hi,
                             __nv_bfloat16* __restrict__ lo, int n4)
{
    int i = blockIdx.x * blockDim.x + threadIdx.x;
    if (i >= n4) return;
    float4 v = reinterpret_cast<const float4*>(src)[i];
    float hx = __bfloat162float(__float2bfloat16(v.x));
    float hy = __bfloat162float(__float2bfloat16(v.y));
    float hz = __bfloat162float(__float2bfloat16(v.z));
    float hw = __bfloat162float(__float2bfloat16(v.w));
    reinterpret_cast<uint2*>(hi)[i] =
        make_uint2(pack_bf16x2(v.x, v.y), pack_bf16x2(v.z, v.w));
    reinterpret_cast<uint2*>(lo)[i] =
        make_uint2(pack_bf16x2(v.x - hx, v.y - hy), pack_bf16x2(v.z - hz, v.w - hw));
}

// ====== pipelined bf16 split GEMM (pre-split operands, 3-MMA ≈ fp32) ==========
// Register-lean inner loop; __launch_bounds__(256,2) forces 2 blocks/SM.
template<int BN>
__global__ __launch_bounds__(256, 2)
void gemm_bs(const __nv_bfloat16* __restrict__ Ah, const __nv_bfloat16* __restrict__ Al,
             const __nv_bfloat16* __restrict__ Bh, const __nv_bfloat16* __restrict__ Bl,
             float* __restrict__ C0, float* __restrict__ C1,
             int kspan, int lda, int ldb, int ldc)
{
    constexpr int BM = 128, BK = 32;
    constexpr int WN = BN / 2;
    constexpr int NT = WN / 8;
    constexpr int PITCH = BK + 8;
    constexpr int OFF_AH = 0;
    constexpr int OFF_AL = BM*PITCH;
    constexpr int OFF_BH = 2*BM*PITCH;
    constexpr int OFF_BL = 2*BM*PITCH + BN*PITCH;
    constexpr int STAGE  = 2*BM*PITCH + 2*BN*PITCH;

    extern __shared__ __align__(16) uint16_t smem[];
    const uint32_t sbase = smem_u32(smem);

    const int tid  = threadIdx.x;
    const int wid  = tid >> 5;
    const int lane = tid & 31;
    const int warp_m = wid & 3;
    const int warp_n = wid >> 2;
    const int m0 = blockIdx.y * BM;
    const int n0 = blockIdx.x * BN;
    const int kbeg = blockIdx.z * kspan;
    const int kend = kbeg + kspan;
    float* C = (blockIdx.z == 0) ? C0 : C1;

    const int ld_r = tid >> 2;
    const int ld_c = (tid & 3) << 3;

    float acc[2][NT][4];
    #pragma unroll
    for (int mt = 0; mt < 2; ++mt)
        #pragma unroll
        for (int nt = 0; nt < NT; ++nt)
            #pragma unroll
            for (int j = 0; j < 4; ++j) acc[mt][nt][j] = 0.f;

    const int a_row = (lane & 15);
    const int a_koff = (lane >> 4) << 3;
    const int b_row = ((lane >> 4) << 3) + (lane & 7);
    const int b_koff = ((lane >> 3) & 1) << 3;

    auto load_stage = [&](int s, int k0) {
        uint32_t base = sbase + (uint32_t)(s*STAGE*2);
        #pragma unroll
        for (int i = 0; i < 2; ++i) {
            int r = ld_r + i*64;
            uint32_t so = base + (uint32_t)((r*PITCH + ld_c)*2);
            cp16(so + OFF_AH*2, Ah + (size_t)(m0+r)*lda + k0 + ld_c);
            cp16(so + OFF_AL*2, Al + (size_t)(m0+r)*lda + k0 + ld_c);
            if (i*64 < BN) {
                cp16(so + OFF_BH*2, Bh + (size_t)(n0+r)*ldb + k0 + ld_c);
                cp16(so + OFF_BL*2, Bl + (size_t)(n0+r)*ldb + k0 + ld_c);
            }
        }
    };

    load_stage(0, kbeg);
    CP_COMMIT();

    int buf = 0;
    for (int k0 = kbeg; k0 < kend; k0 += BK) {
        if (k0 + BK < kend) load_stage(buf ^ 1, k0 + BK);
        CP_COMMIT();
        CP_WAIT1();
        __syncthreads();

        const uint32_t stg = sbase + (uint32_t)(buf*STAGE*2);
        #pragma unroll
        for (int kstep = 0; kstep < 2; ++kstep) {
            uint32_t aH[2][4], aL[2][4];
            #pragma unroll
            for (int mt = 0; mt < 2; ++mt) {
                uint32_t off = (uint32_t)(((warp_m*32 + mt*16 + a_row)*PITCH
                                          + kstep*16 + a_koff) * 2);
                ldsm4(aH[mt], stg + OFF_AH*2 + off);
                ldsm4(aL[mt], stg + OFF_AL*2 + off);
            }
            // B fragments consumed pair-by-pair to keep register pressure low
            #pragma unroll
            for (int p = 0; p < NT/2; ++p) {
                uint32_t off = (uint32_t)(((warp_n*WN + p*16 + b_row)*PITCH
                                          + kstep*16 + b_koff) * 2);
                uint32_t rH[4], rL[4];
                ldsm4(rH, stg + OFF_BH*2 + off);
                ldsm4(rL, stg + OFF_BL*2 + off);
                #pragma unroll
                for (int mt = 0; mt < 2; ++mt) {
                    mma_bf16(acc[mt][2*p],   aH[mt], rH[0], rH[1]);
                    mma_bf16(acc[mt][2*p],   aH[mt], rL[0], rL[1]);
                    mma_bf16(acc[mt][2*p],   aL[mt], rH[0], rH[1]);
                    mma_bf16(acc[mt][2*p+1], aH[mt], rH[2], rH[3]);
                    mma_bf16(acc[mt][2*p+1], aH[mt], rL[2], rL[3]);
                    mma_bf16(acc[mt][2*p+1], aL[mt], rH[2], rH[3]);
                }
            }
        }
        __syncthreads();
        buf ^= 1;
    }

    #pragma unroll
    for (int mt = 0; mt < 2; ++mt) {
        int r0 = m0 + warp_m*32 + mt*16 + (lane >> 2);
        #pragma unroll
        for (int nt = 0; nt < NT; ++nt) {
            int c0 = n0 + warp_n*WN + nt*8 + ((lane & 3) << 1);
            *reinterpret_cast<float2*>(C + (size_t)r0*ldc + c0) =
                make_float2(acc[mt][nt][0], acc[mt][nt][1]);
            *reinterpret_cast<float2*>(C + (size_t)(r0+8)*ldc + c0) =
                make_float2(acc[mt][nt][2], acc[mt][nt][3]);
        }
    }
}

// ---------------- add K-split halves of dbc ----------------------------------
__global__ void add_kernel(int n4)
{
    int i = blockIdx.x * blockDim.x + threadIdx.x;
    if (i >= n4) return;
    float4 a = reinterpret_cast<float4*>(g_dbc)[i];
    float4 b = reinterpret_cast<float4*>(g_dbc2)[i];
    reinterpret_cast<float4*>(g_dbc)[i] =
        make_float4(a.x+b.x, a.y+b.y, a.z+b.z, a.w+b.w);
}

// ---------- conv+silu, streaming (each xi element read once) -----------------
__global__ __launch_bounds__(256)
void conv_silu_kernel(const float* __restrict__ conv_w,
                      const float* __restrict__ conv_b)
{
    const int b  = blockIdx.y;
    const int t0 = blockIdx.x << 5;
    const int tid = threadIdx.x;
    const int d4 = tid << 2;

    float4 cw[4];
    #pragma unroll
    for (int j = 0; j < 4; ++j)
        cw[j] = reinterpret_cast<const float4*>(conv_w)[d4 + j];
    const float4 bb = reinterpret_cast<const float4*>(conv_b)[tid];

    const float* src = g_xi + (size_t)(b*SEQ)*DINNER + d4;
    float4 x0, x1, x2;
    const float4 z4 = make_float4(0.f,0.f,0.f,0.f);
    x0 = (t0 >= 3) ? *reinterpret_cast<const float4*>(src + (size_t)(t0-3)*DINNER) : z4;
    x1 = (t0 >= 2) ? *reinterpret_cast<const float4*>(src + (size_t)(t0-2)*DINNER) : z4;
    x2 = (t0 >= 1) ? *reinterpret_cast<const float4*>(src + (size_t)(t0-1)*DINNER) : z4;

    #pragma unroll 4
    for (int l = t0; l < t0 + 32; ++l) {
        float4 x3 = *reinterpret_cast<const float4*>(src + (size_t)l*DINNER);
        float4 acc;
        acc.x = bb.x + cw[0].x*x0.x + cw[0].y*x1.x + cw[0].z*x2.x + cw[0].w*x3.x;
        acc.y = bb.y + cw[1].x*x0.y + cw[1].y*x1.y + cw[1].z*x2.y + cw[1].w*x3.y;
        acc.z = bb.z + cw[2].x*x0.z + cw[2].y*x1.z + cw[2].z*x2.z + cw[2].w*x3.z;
        acc.w = bb.w + cw[3].x*x0.w + cw[3].y*x1.w + cw[3].z*x2.w + cw[3].w*x3.w;
        acc.x = acc.x / (1.f + __expf(-acc.x));
        acc.y = acc.y / (1.f + __expf(-acc.y));
        acc.z = acc.z / (1.f + __expf(-acc.z));
        acc.w = acc.w / (1.f + __expf(-acc.w));

        size_t o = (size_t)(b*SEQ + l)*DINNER + d4;
        *reinterpret_cast<float4*>(g_xc + o) = acc;
        float hx = __bfloat162float(__float2bfloat16(acc.x));
        float hy = __bfloat162float(__float2bfloat16(acc.y));
        float hz = __bfloat162float(__float2bfloat16(acc.z));
        float hw = __bfloat162float(__float2bfloat16(acc.w));
        *reinterpret_cast<uint2*>(g_xch + o) =
            make_uint2(pack_bf16x2(acc.x, acc.y), pack_bf16x2(acc.z, acc.w));
        *reinterpret_cast<uint2*>(g_xcl + o) =
            make_uint2(pack_bf16x2(acc.x-hx, acc.y-hy), pack_bf16x2(acc.z-hz, acc.w-hw));
        x0 = x1; x1 = x2; x2 = x3;
    }
}

// ---------------- z at the last token only -----------------------------------
__global__ void zlast_kernel(const float* __restrict__ x,
                             const float* __restrict__ W_in)
{
    const int warp = (blockIdx.x * blockDim.x + threadIdx.x) >> 5;
    const int lane = threadIdx.x & 31;
    const int b = warp >> 10;
    const int d = warp & (DINNER - 1);
    const float* xr = x + ((size_t)b*SEQ + (SEQ-1)) * DMODEL;
    const float* wr = W_in + (size_t)(DINNER + d) * DMODEL;
    float acc = 0.f;
    #pragma unroll 4
    for (int k = lane; k < DMODEL; k += 32) acc = fmaf(xr[k], wr[k], acc);
    #pragma unroll
    for (int off = 16; off; off >>= 1) acc += __shfl_down_sync(0xffffffffu, acc, off);
    if (lane == 0) g_zlast[warp] = acc;
}

// ---------------- selective scan with fused dt projection ---------------------
__global__ void scan_kernel(const float* __restrict__ A_log,
                            const float* __restrict__ Dv,
                            const float* __restrict__ W_dt,
                            const float* __restrict__ b_dt)
{
    const int b     = blockIdx.x >> 6;
    const int dbase = (blockIdx.x & 63) << 4;
    const int tid = threadIdx.x;
    const int dl  = tid >> 4;
    const int s   = tid & 15;
    const int d   = dbase + dl;

    __shared__ float s_wdt[16][33];
    __shared__ float s_bdt[16];
    __shared__ float s_r [64][32];
    __shared__ float s_dt[64][16];
    __shared__ float s_u [64][16];
    __shared__ float s_B [64][16];

    #pragma unroll
    for (int e = tid; e < 16*32; e += 256) {
        int c = e >> 5, r = e & 31;
        s_wdt[c][r] = W_dt[(dbase + c)*DTRANK + r];
    }
    if (tid < 16) s_bdt[tid] = b_dt[dbase + tid];

    const float A_s = -__expf(A_log[d*DSTATE + s]);
    float h = 0.f;

    for (int t0 = 0; t0 < SEQ; t0 += 64) {
        __syncthreads();
        #pragma unroll
        for (int i = 0; i < 8; ++i) {
            int idx = tid + i*256;
            int tt = idx >> 5, r = idx & 31;
            s_r[tt][r] = g_dbc[(b*SEQ + t0 + tt)*NDBC + r];
        }
        #pragma unroll
        for (int i = 0; i < 4; ++i) {
            int idx = tid + i*256;
            int tt = idx >> 4, c = idx & 15;
            int m = b*SEQ + t0 + tt;
            s_u[tt][c] = g_xc [m*DINNER + dbase + c];
            s_B[tt][c] = g_dbc[m*NDBC + DTRANK + c];
        }
        __syncthreads();
        #pragma unroll
        for (int i = 0; i < 4; ++i) {
            int idx = tid + i*256;
            int tt = idx >> 4, c = idx & 15;
            float acc = s_bdt[c];
            #pragma unroll
            for (int r = 0; r < 32; ++r)
                acc = fmaf(s_r[tt][r], s_wdt[c][r], acc);
            s_dt[tt][c] = (acc > 20.f) ? acc : log1pf(__expf(acc));
        }
        __syncthreads();
        #pragma unroll 8
        for (int tt = 0; tt < 64; ++tt) {
            float dtv = s_dt[tt][dl];
            h = fmaf(__expf(dtv * A_s), h, (dtv * s_u[tt][dl]) * s_B[tt][s]);
        }
    }

    const int mlast = b*SEQ + (SEQ-1);
    float y = h * g_dbc[mlast*NDBC + DTRANK + DSTATE + s];
    #pragma unroll
    for (int off = 8; off; off >>= 1) y += __shfl_down_sync(0xffffffffu, y, off, 16);
    if (s == 0) {
        float ul = g_xc[mlast*DINNER + d];
        float zl = g_zlast[b*DINNER + d];
        float silu_z = zl / (1.f + __expf(-zl));
        g_ylast[b*DINNER + d] = (y + Dv[d]*ul) * silu_z;
    }
}

// ---------------- tail: out proj + LN + head ----------------------------------
__global__ void final_kernel(const float* __restrict__ W_out,
                             const float* __restrict__ ln_g,
                             const float* __restrict__ ln_b,
                             const float* __restrict__ head_W,
                             const float* __restrict__ head_b,
                             float* __restrict__ out)
{
    const int b = blockIdx.x;
    const int j = threadIdx.x;
    __shared__ float sy[DINNER];
    __shared__ float sn[DMODEL];
    __shared__ float rbuf[DMODEL];

    sy[j]       = g_ylast[b*DINNER + j];
    sy[j + 512] = g_ylast[b*DINNER + 512 + j];
    __syncthreads();

    const float* wr = W_out + (size_t)j * DINNER;
    float a0 = 0.f, a1 = 0.f, a2 = 0.f, a3 = 0.f;
    #pragma unroll 4
    for (int k = 0; k < DINNER; k += 4) {
        float4 w = *reinterpret_cast<const float4*>(wr + k);
        a0 = fmaf(sy[k+0], w.x, a0);
        a1 = fmaf(sy[k+1], w.y, a1);
        a2 = fmaf(sy[k+2], w.z, a2);
        a3 = fmaf(sy[k+3], w.w, a3);
    }
    float last = (a0 + a1) + (a2 + a3);

    rbuf[j] = last;
    __syncthreads();
    #pragma unroll
    for (int st = 256; st > 0; st >>= 1) {
        if (j < st) rbuf[j] += rbuf[j + st];
        __syncthreads();
    }
    float mu = rbuf[0] / (float)DMODEL;
    __syncthreads();
    float diff = last - mu;
    rbuf[j] = diff * diff;
    __syncthreads();
    #pragma unroll
    for (int st = 256; st > 0; st >>= 1) {
        if (j < st) rbuf[j] += rbuf[j + st];
        __syncthreads();
    }
    float rstd = rsqrtf(rbuf[0] / (float)DMODEL + 1e-5f);
    __syncthreads();

    sn[j] = diff * rstd * ln_g[j] + ln_b[j];
    __syncthreads();

    const float* hw = head_W + (size_t)j * DMODEL;
    float h0 = 0.f, h1 = 0.f, h2 = 0.f, h3 = 0.f;
    #pragma unroll 4
    for (int k = 0; k < DMODEL; k += 4) {
        float4 w = *reinterpret_cast<const float4*>(hw + k);
        h0 = fmaf(sn[k+0], w.x, h0);
        h1 = fmaf(sn[k+1], w.y, h1);
        h2 = fmaf(sn[k+2], w.z, h2);
        h3 = fmaf(sn[k+3], w.w, h3);
    }
    out[b*DMODEL + j] = head_b[j] + (h0 + h1) + (h2 + h3);
}

// ---------------- launch --------------------------------------------------------
extern "C" void kernel_launch(void* const* d_in, const int* in_sizes, int n_in,
                              void* d_out, int out_size)
{
    const float* x      = (const float*)d_in[0];
    const float* W_in   = (const float*)d_in[1];
    const float* conv_w = (const float*)d_in[2];
    const float* conv_b = (const float*)d_in[3];
    const float* W_x    = (const float*)d_in[4];
    const float* W_dt   = (const float*)d_in[5];
    const float* b_dt   = (const float*)d_in[6];
    const float* A_log  = (const float*)d_in[7];
    const float* Dv     = (const float*)d_in[8];
    const float* W_out  = (const float*)d_in[9];
    const float* ln_g   = (const float*)d_in[10];
    const float* ln_b   = (const float*)d_in[11];
    const float* head_W = (const float*)d_in[12];
    const float* head_b = (const float*)d_in[13];
    float* out = (float*)d_out;

    float *xi, *xc, *dbc, *dbc2;
    cudaGetSymbolAddress((void**)&xi,   g_xi);
    cudaGetSymbolAddress((void**)&xc,   g_xc);
    cudaGetSymbolAddress((void**)&dbc,  g_dbc);
    cudaGetSymbolAddress((void**)&dbc2, g_dbc2);
    __nv_bfloat16 *xh, *xl, *wih, *wil, *wxh, *wxl, *xch, *xcl;
    cudaGetSymbolAddress((void**)&xh,  g_xh);
    cudaGetSymbolAddress((void**)&xl,  g_xl);
    cudaGetSymbolAddress((void**)&wih, g_wih);
    cudaGetSymbolAddress((void**)&wil, g_wil);
    cudaGetSymbolAddress((void**)&wxh, g_wxh);
    cudaGetSymbolAddress((void**)&wxl, g_wxl);
    cudaGetSymbolAddress((void**)&xch, g_xch);
    cudaGetSymbolAddress((void**)&xcl, g_xcl);

    const int SMEM128 = (2*128*40 + 2*128*40) * 2 * 2;  // 81920
    const int SMEM64  = (2*128*40 + 2*64*40)  * 2 * 2;  // 61440
    cudaFuncSetAttribute(gemm_bs<128>, cudaFuncAttributeMaxDynamicSharedMemorySize, SMEM128);
    cudaFuncSetAttribute(gemm_bs<64>,  cudaFuncAttributeMaxDynamicSharedMemorySize, SMEM64);

    split_kernel<<<(MTOK*DMODEL/4 + 255)/256, 256>>>(x, xh, xl, MTOK*DMODEL/4);
    split_kernel<<<(DINNER*DMODEL/4 + 255)/256, 256>>>(W_in, wih, wil, DINNER*DMODEL/4);
    split_kernel<<<(NDBC*DINNER/4 + 255)/256, 256>>>(W_x, wxh, wxl, NDBC*DINNER/4);
    zlast_kernel<<<(BATCH*DINNER*32)/256, 256>>>(x, W_in);

    // K1: xi = x @ W_in[:1024].T
    gemm_bs<128><<<dim3(DINNER/128, MTOK/128, 1), 256, SMEM128>>>(
        xh, xl, wih, wil, xi, xi, DMODEL, DMODEL, DMODEL, DINNER);

    // conv + silu (+ bf16 hi/lo emit for K3)
    conv_silu_kernel<<<dim3(32, 8), 256>>>(conv_w, conv_b);

    // K3: dbc = xc @ W_x.T, K split in 2 (z-dim)
    gemm_bs<64><<<dim3(1, MTOK/128, 2), 256, SMEM64>>>(
        xch, xcl, wxh, wxl, dbc, dbc2, DINNER/2, DINNER, DINNER, NDBC);
    add_kernel<<<(MTOK*NDBC/4 + 255)/256, 256>>>(MTOK*NDBC/4);

    scan_kernel<<<BATCH * (DINNER/16), 256>>>(A_log, Dv, W_dt, b_dt);
    final_kernel<<<BATCH, DMODEL>>>(W_out, ln_g, ln_b, head_W, head_b, out);
}